// round 8
// baseline (speedup 1.0000x reference)
#include <cuda_runtime.h>
#include <cuda_fp16.h>
#include <cstdint>
#include <math.h>

// ===========================================================================
// CapsNet forward, B=512 — Round 8: Round 7 direct-LDG conv2 with the K-step
// units bug fixed (stride 16 halfs per m16n8k16, 16 steps cover all 256 c).
// ===========================================================================

// ------------------------------ scratch ------------------------------------
__device__ __half g_h1t   [512u * 400u * 256u];            // 105 MB NHWC fp16
__device__ __half g_w2t_hi[81u * 256u * 256u];             // 10.6 MB
__device__ __half g_w2t_lo[81u * 256u * 256u];
__device__ float  g_h2[512u * 9216u];
__device__ float  g_u [512u * 9216u];
__device__ __half g_uhat_h[512u * 1152u * 160u];           // 188.7 MB fp16
__device__ float  g_spart[9u * 512u * 160u];
__device__ float  g_vsum[512u * 160u];

// ------------------------------ helpers ------------------------------------
__device__ __forceinline__ void mma16816h(float* c, const uint32_t* a,
                                          const uint32_t* b) {
    asm volatile("mma.sync.aligned.m16n8k16.row.col.f32.f16.f16.f32 "
                 "{%0,%1,%2,%3}, {%4,%5,%6,%7}, {%8,%9}, {%0,%1,%2,%3};"
                 : "+f"(c[0]), "+f"(c[1]), "+f"(c[2]), "+f"(c[3])
                 : "r"(a[0]), "r"(a[1]), "r"(a[2]), "r"(a[3]),
                   "r"(b[0]), "r"(b[1]));
}
__device__ __forceinline__ uint32_t ldg32(const __half* p) {
    return __ldg((const uint32_t*)p);
}

// ---------------------------------------------------------------------------
// conv1 + relu -> single fp16 NHWC. grid (512, 8), block 256, 72512 B smem.
// ---------------------------------------------------------------------------
__global__ __launch_bounds__(256) void k_conv1(const float* __restrict__ x,
                                               const float* __restrict__ w1,
                                               const float* __restrict__ b1)
{
    extern __shared__ __align__(16) char c1smem[];
    float* xs = (float*)c1smem;
    float* ws = xs + 2352;
    __half* st = (__half*)(c1smem + 40512);

    const int b  = blockIdx.x;
    const int cg = blockIdx.y;
    const int id = threadIdx.x;
    {
        const float4* xg = (const float4*)(x + b * 2352);
        float4* xs4 = (float4*)xs;
        for (int i = id; i < 588; i += 256) xs4[i] = xg[i];
        const float4* wg = (const float4*)(w1 + cg * 7776);
        float4* ws4 = (float4*)ws;
        for (int i = id; i < 1944; i += 256) ws4[i] = wg[i];
    }
    __syncthreads();
    const int ty = id & 3;
    const int tx = id >> 2;
    float bias[8];
#pragma unroll
    for (int i = 0; i < 8; i++) bias[i] = b1[cg * 32 + ty + 4 * i];

    for (int qi = 0; qi < 2; qi++) {
        int gq = tx + 64 * qi;
        if (gq < 100) {
            int oy  = gq / 5;
            int oxb = (gq % 5) * 4;
            float acc[8][4];
#pragma unroll
            for (int i = 0; i < 8; i++)
#pragma unroll
                for (int j = 0; j < 4; j++) acc[i][j] = 0.f;
            for (int c = 0; c < 3; c++) {
                for (int ky = 0; ky < 9; ky++) {
                    const float* xrow = &xs[(c * 28 + oy + ky) * 28 + oxb];
                    float rin[12];
                    *(float4*)(rin)     = *(const float4*)(xrow);
                    *(float4*)(rin + 4) = *(const float4*)(xrow + 4);
                    *(float4*)(rin + 8) = *(const float4*)(xrow + 8);
                    const int kb = c * 81 + ky * 9;
#pragma unroll
                    for (int kx = 0; kx < 9; kx++) {
#pragma unroll
                        for (int i = 0; i < 8; i++) {
                            float w = ws[(ty + 4 * i) * 243 + kb + kx];
                            acc[i][0] = fmaf(w, rin[kx],     acc[i][0]);
                            acc[i][1] = fmaf(w, rin[kx + 1], acc[i][1]);
                            acc[i][2] = fmaf(w, rin[kx + 2], acc[i][2]);
                            acc[i][3] = fmaf(w, rin[kx + 3], acc[i][3]);
                        }
                    }
                }
            }
#pragma unroll
            for (int i = 0; i < 8; i++) {
                const int ch = ty + 4 * i;
#pragma unroll
                for (int j = 0; j < 4; j++) {
                    const int pix = gq * 4 + j;
                    st[pix * 40 + ch] =
                        __float2half(fmaxf(acc[i][j] + bias[i], 0.f));
                }
            }
        }
    }
    __syncthreads();

    for (int f = id; f < 1600; f += 256) {
        const int pix = f >> 2;
        const int j   = f & 3;
        const size_t dst = ((size_t)b * 400 + pix) * 256 + cg * 32 + j * 8;
        *(uint4*)&g_h1t[dst] = *(const uint4*)&st[pix * 40 + j * 8];
    }
}

// ---------------------------------------------------------------------------
// W2 [co][c][9][9] -> [kykx][co][c] fp16 hi/lo. grid 256, block 256.
// ---------------------------------------------------------------------------
__global__ __launch_bounds__(256) void k_wprep(const float* __restrict__ w2)
{
    __shared__ float wt[128 * 81];
    const int co  = blockIdx.x;
    const int id  = threadIdx.x;
    const int c   = id & 127;
    const int hf  = id >> 7;

    for (int cc = 0; cc < 2; cc++) {
        __syncthreads();
        const float* src = w2 + (size_t)co * 20736 + cc * 128 * 81;
        for (int i = id; i < 128 * 81; i += 256) wt[i] = src[i];
        __syncthreads();
        const int k0 = hf ? 41 : 0;
        const int k1 = hf ? 81 : 41;
        for (int kk = k0; kk < k1; kk++) {
            float v = wt[c * 81 + kk];
            __half h = __float2half(v);
            size_t d = ((size_t)kk * 256 + co) * 256 + cc * 128 + c;
            g_w2t_hi[d] = h;
            g_w2t_lo[d] = __float2half(v - __half2float(h));
        }
    }
}

// ---------------------------------------------------------------------------
// conv2 implicit GEMM, direct-LDG fragments. grid (72, 2), block 512, NO smem.
// CTA tile M=128 x N=256; warps 4(M) x 4(N), warp tile 32x64.
// 81 taps x 16 k16-steps (stride 16 halfs — covers all 256 channels).
// ---------------------------------------------------------------------------
__global__ __launch_bounds__(512) void k_conv2mma(const float* __restrict__ b2)
{
    const int tid  = threadIdx.x;
    const int warp = tid >> 5;
    const int lane = tid & 31;
    const int n0     = blockIdx.x * 256;
    const int coBase = blockIdx.y * 128;
    const int mwarp = warp & 3;       // co: mwarp*32
    const int nwarp = warp >> 2;      // n : nwarp*64

    const uint32_t aRow = (uint32_t)(coBase + mwarp * 32 + (lane >> 2));
    const uint32_t aCol = (uint32_t)((lane & 3) * 2);

    uint32_t bOff[8];
#pragma unroll
    for (int nf = 0; nf < 8; nf++) {
        const int n    = n0 + nwarp * 64 + nf * 8 + (lane >> 2);
        const int bimg = n / 36;
        const int pos  = n - bimg * 36;
        const int oy   = pos / 6, ox = pos - oy * 6;
        bOff[nf] = (uint32_t)((bimg * 400 + oy * 40 + ox * 2) * 256
                              + (lane & 3) * 2);
    }

    float acc[2][8][4];
#pragma unroll
    for (int mf = 0; mf < 2; mf++)
#pragma unroll
        for (int nf = 0; nf < 8; nf++)
#pragma unroll
            for (int i = 0; i < 4; i++) acc[mf][nf][i] = 0.f;

    for (int kk = 0; kk < 81; kk++) {
        const int ky = kk / 9, kx = kk - ky * 9;
        const uint32_t bTap  = (uint32_t)((ky * 20 + kx) * 256);
        const uint32_t aBase = (kk * 256u + aRow) * 256u + aCol;
#pragma unroll 1
        for (int cq = 0; cq < 4; cq++) {        // c block of 64
#pragma unroll
            for (int q = 0; q < 4; q++) {       // k16 step (stride 16 halfs)
                const uint32_t qo = cq * 64 + q * 16;
                uint32_t B[8][2];
#pragma unroll
                for (int nf = 0; nf < 8; nf++) {
                    const __half* p = g_h1t + bOff[nf] + bTap + qo;
                    B[nf][0] = ldg32(p);
                    B[nf][1] = ldg32(p + 8);
                }
#pragma unroll
                for (int mf = 0; mf < 2; mf++) {
                    const uint32_t off = aBase + (uint32_t)(mf * 16) * 256u + qo;
                    const __half* ph = g_w2t_hi + off;
                    const __half* pl = g_w2t_lo + off;
                    uint32_t Ah[4], Al[4];
                    Ah[0] = ldg32(ph);
                    Ah[1] = ldg32(ph + 8 * 256);
                    Ah[2] = ldg32(ph + 8);
                    Ah[3] = ldg32(ph + 8 * 256 + 8);
                    Al[0] = ldg32(pl);
                    Al[1] = ldg32(pl + 8 * 256);
                    Al[2] = ldg32(pl + 8);
                    Al[3] = ldg32(pl + 8 * 256 + 8);
#pragma unroll
                    for (int nf = 0; nf < 8; nf++) {
                        float* c = acc[mf][nf];
                        mma16816h(c, Ah, B[nf]);
                        mma16816h(c, Al, B[nf]);
                    }
                }
            }
        }
    }

    // epilogue: bias + store to h2 [b][co][pos]
#pragma unroll
    for (int mf = 0; mf < 2; mf++) {
        const int coB = coBase + mwarp * 32 + mf * 16 + (lane >> 2);
        const float bias0 = b2[coB];
        const float bias1 = b2[coB + 8];
#pragma unroll
        for (int nf = 0; nf < 8; nf++) {
#pragma unroll
            for (int i = 0; i < 4; i++) {
                const int co = coB + ((i >> 1) << 3);
                const int n  = n0 + nwarp * 64 + nf * 8 + ((lane & 3) << 1) + (i & 1);
                const int bi = n / 36;
                const int pp = n - bi * 36;
                g_h2[(size_t)bi * 9216 + co * 36 + pp] =
                    acc[mf][nf][i] + ((i >> 1) ? bias1 : bias0);
            }
        }
    }
}

// ---------------------------------------------------------------------------
// primary capsule squash (unchanged)
// ---------------------------------------------------------------------------
__global__ __launch_bounds__(256) void k_squash_pc()
{
    unsigned idx = blockIdx.x * 256u + threadIdx.x;
    if (idx >= 589824u) return;
    const float4* p = (const float4*)(g_h2 + (size_t)idx * 8);
    float4 a = p[0], b = p[1];
    float sn = a.x*a.x + a.y*a.y + a.z*a.z + a.w*a.w
             + b.x*b.x + b.y*b.y + b.z*b.z + b.w*b.w;
    float sc = sn / ((1.f + sn) * (sqrtf(sn) + 1e-6f));
    a.x *= sc; a.y *= sc; a.z *= sc; a.w *= sc;
    b.x *= sc; b.y *= sc; b.z *= sc; b.w *= sc;
    float4* q = (float4*)(g_u + (size_t)idx * 8);
    q[0] = a; q[1] = b;
}

// ---------------------------------------------------------------------------
// u_hat -> fp16 (unchanged)
// ---------------------------------------------------------------------------
__global__ __launch_bounds__(256) void k_uhat(const float* __restrict__ W)
{
    __shared__ float Wsm[4 * 1280];
    __shared__ float usm[64 * 32];
    const int capg = blockIdx.x * 4;
    const int img0 = blockIdx.y * 64;
    const int id   = threadIdx.x;
    {
        const float4* Wg = (const float4*)(W + (size_t)capg * 1280);
        float4* Ws4 = (float4*)Wsm;
        for (int i = id; i < 1280; i += 256) Ws4[i] = Wg[i];
        float4* us4 = (float4*)usm;
        for (int i = id; i < 512; i += 256) {
            int im = i >> 3, r = i & 7;
            us4[i] = *(const float4*)(g_u + (size_t)(img0 + im) * 9216
                                      + capg * 8 + r * 4);
        }
    }
    __syncthreads();
    for (int it = 0; it < 40; it++) {
        int flat = it * 256 + id;
        int oe4  = flat % 40;
        int cap  = (flat / 40) & 3;
        int im   = flat / 160;
        int o    = oe4 >> 2;
        int e0   = (oe4 & 3) * 4;
        const float*  up = &usm[im * 32 + cap * 8];
        const float4* Wp = (const float4*)&Wsm[cap * 1280 + o * 128 + e0];
        float4 acc = make_float4(0.f, 0.f, 0.f, 0.f);
#pragma unroll
        for (int d = 0; d < 8; d++) {
            float  ud = up[d];
            float4 w4 = Wp[d * 4];
            acc.x = fmaf(ud, w4.x, acc.x);
            acc.y = fmaf(ud, w4.y, acc.y);
            acc.z = fmaf(ud, w4.z, acc.z);
            acc.w = fmaf(ud, w4.w, acc.w);
        }
        __half2 h0 = __floats2half2_rn(acc.x, acc.y);
        __half2 h1 = __floats2half2_rn(acc.z, acc.w);
        uint2 pk = make_uint2(*(uint32_t*)&h0, *(uint32_t*)&h1);
        *(uint2*)&g_uhat_h[((size_t)(img0 + im) * 1152 + capg + cap) * 160
                           + o * 16 + e0] = pk;
    }
}

// ---------------------------------------------------------------------------
// fused routing iteration, smem-staged (unchanged)
// ---------------------------------------------------------------------------
__global__ __launch_bounds__(160) void k_route(int uniform)
{
    __shared__ __align__(16) __half tile[128 * 168];
    __shared__ float vs[160];
    __shared__ float c_sm[128][10];
    const int b     = blockIdx.x;
    const int chunk = blockIdx.y;
    const int tid   = threadIdx.x;
    const __half* ub = g_uhat_h + (size_t)b * 184320 + (size_t)chunk * 128 * 160;

    if (uniform) {
        const int oe = tid;
        float acc = 0.f;
#pragma unroll 4
        for (int cap = 0; cap < 128; cap++)
            acc += __half2float(ub[(size_t)cap * 160 + oe]);
        g_spart[((size_t)chunk * 512 + b) * 160 + oe] = acc * 0.1f;
        return;
    }

    vs[tid] = g_vsum[b * 160 + tid];
    for (int f = tid; f < 2560; f += 160) {
        const int r = f / 20, j = f % 20;
        *(uint4*)&tile[r * 168 + j * 8] = *(const uint4*)(ub + (size_t)r * 160 + j * 8);
    }
    __syncthreads();

    if (tid < 128) {
        const __half2* row = (const __half2*)&tile[tid * 168];
        float t[10];
#pragma unroll
        for (int o = 0; o < 10; o++) {
            float s = 0.f;
#pragma unroll
            for (int e2 = 0; e2 < 8; e2++) {
                float2 f = __half22float2(row[o * 8 + e2]);
                s += f.x * vs[o * 16 + e2 * 2] + f.y * vs[o * 16 + e2 * 2 + 1];
            }
            t[o] = s;
        }
        float m = t[0];
#pragma unroll
        for (int o = 1; o < 10; o++) m = fmaxf(m, t[o]);
        float se = 0.f;
#pragma unroll
        for (int o = 0; o < 10; o++) { t[o] = expf(t[o] - m); se += t[o]; }
        float inv = 1.f / se;
#pragma unroll
        for (int o = 0; o < 10; o++) c_sm[tid][o] = t[o] * inv;
    }
    __syncthreads();

    const int oe = tid;
    const int o  = oe >> 4;
    float acc = 0.f;
#pragma unroll 4
    for (int cap = 0; cap < 128; cap++)
        acc = fmaf(c_sm[cap][o], __half2float(tile[cap * 168 + oe]), acc);
    g_spart[((size_t)chunk * 512 + b) * 160 + oe] = acc;
}

// ---------------------------------------------------------------------------
// sum partials + squash (unchanged)
// ---------------------------------------------------------------------------
__global__ void k_squash_v(float* __restrict__ out, int mode)
{
    int idx = blockIdx.x * 256 + threadIdx.x;
    if (idx >= 5120) return;
    float4 r[4];
#pragma unroll
    for (int i = 0; i < 4; i++) r[i] = make_float4(0.f, 0.f, 0.f, 0.f);
#pragma unroll
    for (int p = 0; p < 9; p++) {
        const float4* sp = (const float4*)(g_spart + (size_t)p * 81920
                                           + (size_t)idx * 16);
#pragma unroll
        for (int i = 0; i < 4; i++) {
            float4 v = sp[i];
            r[i].x += v.x; r[i].y += v.y; r[i].z += v.z; r[i].w += v.w;
        }
    }
    float sn = 0.f;
#pragma unroll
    for (int i = 0; i < 4; i++)
        sn += r[i].x*r[i].x + r[i].y*r[i].y + r[i].z*r[i].z + r[i].w*r[i].w;
    float sc = sn / ((1.f + sn) * (sqrtf(sn) + 1e-6f));
#pragma unroll
    for (int i = 0; i < 4; i++) {
        r[i].x *= sc; r[i].y *= sc; r[i].z *= sc; r[i].w *= sc;
    }
    if (mode == 0) {
        float4* q = (float4*)(g_vsum + (size_t)idx * 16);
#pragma unroll
        for (int i = 0; i < 4; i++) q[i] = r[i];
    } else if (mode == 1) {
        float4* q = (float4*)(g_vsum + (size_t)idx * 16);
#pragma unroll
        for (int i = 0; i < 4; i++) {
            float4 old = q[i];
            old.x += r[i].x; old.y += r[i].y; old.z += r[i].z; old.w += r[i].w;
            q[i] = old;
        }
    } else {
        float4* q = (float4*)(out + (size_t)idx * 16);
#pragma unroll
        for (int i = 0; i < 4; i++) q[i] = r[i];
    }
}

// ---------------------------------------------------------------------------
extern "C" void kernel_launch(void* const* d_in, const int* in_sizes, int n_in,
                              void* d_out, int out_size)
{
    const float* x   = (const float*)d_in[0];
    const float* w1  = (const float*)d_in[1];
    const float* b1  = (const float*)d_in[2];
    const float* w2  = (const float*)d_in[3];
    const float* b2  = (const float*)d_in[4];
    const float* W   = (const float*)d_in[5];
    float* out = (float*)d_out;

    cudaFuncSetAttribute(k_conv1,
                         cudaFuncAttributeMaxDynamicSharedMemorySize, 72512);

    k_conv1<<<dim3(512, 8), 256, 72512>>>(x, w1, b1);
    k_wprep<<<256, 256>>>(w2);
    k_conv2mma<<<dim3(72, 2), 512>>>(b2);
    k_squash_pc<<<2304, 256>>>();
    k_uhat<<<dim3(288, 8), 256>>>(W);

    k_route<<<dim3(512, 9), 160>>>(1);       // iter 0: uniform c
    k_squash_v<<<20, 256>>>(nullptr, 0);     // vsum = v0
    k_route<<<dim3(512, 9), 160>>>(0);       // iter 1
    k_squash_v<<<20, 256>>>(nullptr, 1);     // vsum += v1
    k_route<<<dim3(512, 9), 160>>>(0);       // iter 2
    k_squash_v<<<20, 256>>>(out, 2);         // out = v2
}

// round 9
// speedup vs baseline: 1.9371x; 1.9371x over previous
#include <cuda_runtime.h>
#include <cuda_fp16.h>
#include <cstdint>
#include <math.h>

// ===========================================================================
// CapsNet forward, B=512 — Round 9: revert conv2 to R6 cp.async pipeline
// (direct-LDG experiment regressed), drop weight lo-term (single fp16 A):
// stage 48KB/chunk (Ah16|B32), halved MMA count.
// ===========================================================================

// ------------------------------ scratch ------------------------------------
__device__ __half g_h1t [512u * 400u * 256u];              // 105 MB NHWC fp16
__device__ __half g_w2t [81u * 256u * 256u];               // 10.6 MB fp16
__device__ float  g_h2[512u * 9216u];
__device__ float  g_u [512u * 9216u];
__device__ __half g_uhat_h[512u * 1152u * 160u];           // 188.7 MB fp16
__device__ float  g_spart[9u * 512u * 160u];
__device__ float  g_vsum[512u * 160u];

// ------------------------------ PTX helpers --------------------------------
__device__ __forceinline__ uint32_t smem_u32(const void* p) {
    uint32_t a;
    asm("{ .reg .u64 t; cvta.to.shared.u64 t, %1; cvt.u32.u64 %0, t; }"
        : "=r"(a) : "l"(p));
    return a;
}
#define CP16(dst, src) \
    asm volatile("cp.async.cg.shared.global [%0], [%1], 16;" :: "r"(dst), "l"(src) : "memory")
#define CP_COMMIT() asm volatile("cp.async.commit_group;" ::: "memory")
#define CP_WAIT1()  asm volatile("cp.async.wait_group 1;" ::: "memory")
#define CP_WAIT0()  asm volatile("cp.async.wait_group 0;" ::: "memory")

__device__ __forceinline__ void ldsm_x4(uint32_t* r, uint32_t addr) {
    asm volatile("ldmatrix.sync.aligned.m8n8.x4.shared.b16 {%0,%1,%2,%3}, [%4];"
                 : "=r"(r[0]), "=r"(r[1]), "=r"(r[2]), "=r"(r[3]) : "r"(addr));
}
__device__ __forceinline__ void mma16816h(float* c, const uint32_t* a,
                                          const uint32_t* b) {
    asm volatile("mma.sync.aligned.m16n8k16.row.col.f32.f16.f16.f32 "
                 "{%0,%1,%2,%3}, {%4,%5,%6,%7}, {%8,%9}, {%0,%1,%2,%3};"
                 : "+f"(c[0]), "+f"(c[1]), "+f"(c[2]), "+f"(c[3])
                 : "r"(a[0]), "r"(a[1]), "r"(a[2]), "r"(a[3]),
                   "r"(b[0]), "r"(b[1]));
}
__device__ __forceinline__ uint32_t swz(uint32_t o) {
    return o ^ ((o >> 3) & 0x70);
}

// ---------------------------------------------------------------------------
// conv1 + relu -> single fp16 NHWC. grid (512, 8), block 256, 72512 B smem.
// ---------------------------------------------------------------------------
__global__ __launch_bounds__(256) void k_conv1(const float* __restrict__ x,
                                               const float* __restrict__ w1,
                                               const float* __restrict__ b1)
{
    extern __shared__ __align__(16) char c1smem[];
    float* xs = (float*)c1smem;
    float* ws = xs + 2352;
    __half* st = (__half*)(c1smem + 40512);

    const int b  = blockIdx.x;
    const int cg = blockIdx.y;
    const int id = threadIdx.x;
    {
        const float4* xg = (const float4*)(x + b * 2352);
        float4* xs4 = (float4*)xs;
        for (int i = id; i < 588; i += 256) xs4[i] = xg[i];
        const float4* wg = (const float4*)(w1 + cg * 7776);
        float4* ws4 = (float4*)ws;
        for (int i = id; i < 1944; i += 256) ws4[i] = wg[i];
    }
    __syncthreads();
    const int ty = id & 3;
    const int tx = id >> 2;
    float bias[8];
#pragma unroll
    for (int i = 0; i < 8; i++) bias[i] = b1[cg * 32 + ty + 4 * i];

    for (int qi = 0; qi < 2; qi++) {
        int gq = tx + 64 * qi;
        if (gq < 100) {
            int oy  = gq / 5;
            int oxb = (gq % 5) * 4;
            float acc[8][4];
#pragma unroll
            for (int i = 0; i < 8; i++)
#pragma unroll
                for (int j = 0; j < 4; j++) acc[i][j] = 0.f;
            for (int c = 0; c < 3; c++) {
                for (int ky = 0; ky < 9; ky++) {
                    const float* xrow = &xs[(c * 28 + oy + ky) * 28 + oxb];
                    float rin[12];
                    *(float4*)(rin)     = *(const float4*)(xrow);
                    *(float4*)(rin + 4) = *(const float4*)(xrow + 4);
                    *(float4*)(rin + 8) = *(const float4*)(xrow + 8);
                    const int kb = c * 81 + ky * 9;
#pragma unroll
                    for (int kx = 0; kx < 9; kx++) {
#pragma unroll
                        for (int i = 0; i < 8; i++) {
                            float w = ws[(ty + 4 * i) * 243 + kb + kx];
                            acc[i][0] = fmaf(w, rin[kx],     acc[i][0]);
                            acc[i][1] = fmaf(w, rin[kx + 1], acc[i][1]);
                            acc[i][2] = fmaf(w, rin[kx + 2], acc[i][2]);
                            acc[i][3] = fmaf(w, rin[kx + 3], acc[i][3]);
                        }
                    }
                }
            }
#pragma unroll
            for (int i = 0; i < 8; i++) {
                const int ch = ty + 4 * i;
#pragma unroll
                for (int j = 0; j < 4; j++) {
                    const int pix = gq * 4 + j;
                    st[pix * 40 + ch] =
                        __float2half(fmaxf(acc[i][j] + bias[i], 0.f));
                }
            }
        }
    }
    __syncthreads();

    for (int f = id; f < 1600; f += 256) {
        const int pix = f >> 2;
        const int j   = f & 3;
        const size_t dst = ((size_t)b * 400 + pix) * 256 + cg * 32 + j * 8;
        *(uint4*)&g_h1t[dst] = *(const uint4*)&st[pix * 40 + j * 8];
    }
}

// ---------------------------------------------------------------------------
// W2 [co][c][9][9] -> [kykx][co][c] single fp16. grid 256, block 256.
// ---------------------------------------------------------------------------
__global__ __launch_bounds__(256) void k_wprep(const float* __restrict__ w2)
{
    __shared__ float wt[128 * 81];
    const int co  = blockIdx.x;
    const int id  = threadIdx.x;
    const int c   = id & 127;
    const int hf  = id >> 7;

    for (int cc = 0; cc < 2; cc++) {
        __syncthreads();
        const float* src = w2 + (size_t)co * 20736 + cc * 128 * 81;
        for (int i = id; i < 128 * 81; i += 256) wt[i] = src[i];
        __syncthreads();
        const int k0 = hf ? 41 : 0;
        const int k1 = hf ? 81 : 41;
        for (int kk = k0; kk < k1; kk++) {
            g_w2t[((size_t)kk * 256 + co) * 256 + cc * 128 + c] =
                __float2half(wt[c * 81 + kk]);
        }
    }
}

// ---------------------------------------------------------------------------
// conv2 implicit GEMM via mma.sync, 512 threads. grid (72, 2), 98304 B smem.
// CTA tile M=128 x N=256; 324 K64 chunks; warps 4(M) x 4(N), warp tile 32x64.
// Single fp16 term A*B. Stage 49152 B: A[16K] B[32K]; 2 stages.
// ---------------------------------------------------------------------------
#define STAGE_BYTES 49152
#define A_OFF 0
#define B_OFF 16384
#define NCHUNK 324

__device__ __forceinline__ void load_chunk(
    uint32_t stbase, int kk, int c0, int tid,
    int bimg, int oy, int ox, int coBase)
{
    const int ky = kk / 9, kx = kk - ky * 9;
    if (tid < 256) {
        const size_t pix = (size_t)bimg * 400 + (2 * oy + ky) * 20 + (2 * ox + kx);
        const __half* src = g_h1t + pix * 256 + c0;
        const uint32_t dst = stbase + B_OFF;
#pragma unroll
        for (int u = 0; u < 8; u++) {
            uint32_t ob = swz(tid * 128 + u * 16);
            CP16(dst + ob, src + u * 8);
        }
    } else if (tid < 384) {
        const int row = tid - 256;
        const __half* src = g_w2t + ((size_t)kk * 256 + coBase + row) * 256 + c0;
        const uint32_t dst = stbase + A_OFF;
#pragma unroll
        for (int u = 0; u < 8; u++) {
            uint32_t oa = swz(row * 128 + u * 16);
            CP16(dst + oa, src + u * 8);
        }
    }
}

__global__ __launch_bounds__(512) void k_conv2mma(const float* __restrict__ b2)
{
    extern __shared__ __align__(1024) char dynsmem[];
    const uint32_t sb = smem_u32(dynsmem);
    const int tid  = threadIdx.x;
    const int warp = tid >> 5;
    const int lane = tid & 31;
    const int n0     = blockIdx.x * 256;
    const int coBase = blockIdx.y * 128;
    const int mwarp = warp & 3;       // co: mwarp*32
    const int nwarp = warp >> 2;      // n : nwarp*64

    // loader role
    const int nB   = n0 + (tid & 255);
    const int bimg = nB / 36;
    const int pos  = nB - bimg * 36;
    const int oy   = pos / 6, ox = pos - oy * 6;

    // ldmatrix lane addressing
    const int aRowSub = lane & 15;
    const int aColSel = (lane >> 4) * 16;
    const int bMat    = lane >> 3;
    const int bSub    = lane & 7;
    const int bNfSel  = bMat >> 1;
    const int bKSel   = (bMat & 1) * 16;

    float acc[2][8][4];
#pragma unroll
    for (int mf = 0; mf < 2; mf++)
#pragma unroll
        for (int nf = 0; nf < 8; nf++)
#pragma unroll
            for (int i = 0; i < 4; i++) acc[mf][nf][i] = 0.f;

    load_chunk(sb, 0, 0, tid, bimg, oy, ox, coBase);
    CP_COMMIT();

    for (int t = 0; t < NCHUNK; t++) {
        const int s = t & 1, s2 = s ^ 1;
        if (t + 1 < NCHUNK) {
            const int tn = t + 1;
            load_chunk(sb + s2 * STAGE_BYTES, tn >> 2, (tn & 3) * 64,
                       tid, bimg, oy, ox, coBase);
            CP_COMMIT();
            CP_WAIT1();
        } else {
            CP_WAIT0();
        }
        __syncthreads();

        const uint32_t stb = sb + s * STAGE_BYTES;
        const uint32_t aa = stb + A_OFF;
        const uint32_t bb = stb + B_OFF;

#pragma unroll
        for (int q = 0; q < 4; q++) {
            const int qb = q * 32;
            uint32_t B[8][2];
#pragma unroll
            for (int gp = 0; gp < 4; gp++) {
                uint32_t off = swz((nwarp * 64 + (gp * 2 + bNfSel) * 8 + bSub) * 128
                                   + qb + bKSel);
                uint32_t r[4];
                ldsm_x4(r, bb + off);
                B[gp*2][0] = r[0]; B[gp*2][1] = r[1];
                B[gp*2+1][0] = r[2]; B[gp*2+1][1] = r[3];
            }
#pragma unroll
            for (int mf = 0; mf < 2; mf++) {
                uint32_t A[4];
                uint32_t offA = swz((mwarp * 32 + mf * 16 + aRowSub) * 128
                                    + qb + aColSel);
                ldsm_x4(A, aa + offA);
#pragma unroll
                for (int nf = 0; nf < 8; nf++)
                    mma16816h(acc[mf][nf], A, B[nf]);
            }
        }
        __syncthreads();
    }

    // epilogue: bias + store to h2 [b][co][pos]
#pragma unroll
    for (int mf = 0; mf < 2; mf++) {
        const int coB = coBase + mwarp * 32 + mf * 16 + (lane >> 2);
        const float bias0 = b2[coB];
        const float bias1 = b2[coB + 8];
#pragma unroll
        for (int nf = 0; nf < 8; nf++) {
#pragma unroll
            for (int i = 0; i < 4; i++) {
                const int co = coB + ((i >> 1) << 3);
                const int n  = n0 + nwarp * 64 + nf * 8 + ((lane & 3) << 1) + (i & 1);
                const int bi = n / 36;
                const int pp = n - bi * 36;
                g_h2[(size_t)bi * 9216 + co * 36 + pp] =
                    acc[mf][nf][i] + ((i >> 1) ? bias1 : bias0);
            }
        }
    }
}

// ---------------------------------------------------------------------------
// primary capsule squash (unchanged)
// ---------------------------------------------------------------------------
__global__ __launch_bounds__(256) void k_squash_pc()
{
    unsigned idx = blockIdx.x * 256u + threadIdx.x;
    if (idx >= 589824u) return;
    const float4* p = (const float4*)(g_h2 + (size_t)idx * 8);
    float4 a = p[0], b = p[1];
    float sn = a.x*a.x + a.y*a.y + a.z*a.z + a.w*a.w
             + b.x*b.x + b.y*b.y + b.z*b.z + b.w*b.w;
    float sc = sn / ((1.f + sn) * (sqrtf(sn) + 1e-6f));
    a.x *= sc; a.y *= sc; a.z *= sc; a.w *= sc;
    b.x *= sc; b.y *= sc; b.z *= sc; b.w *= sc;
    float4* q = (float4*)(g_u + (size_t)idx * 8);
    q[0] = a; q[1] = b;
}

// ---------------------------------------------------------------------------
// u_hat -> fp16 (unchanged)
// ---------------------------------------------------------------------------
__global__ __launch_bounds__(256) void k_uhat(const float* __restrict__ W)
{
    __shared__ float Wsm[4 * 1280];
    __shared__ float usm[64 * 32];
    const int capg = blockIdx.x * 4;
    const int img0 = blockIdx.y * 64;
    const int id   = threadIdx.x;
    {
        const float4* Wg = (const float4*)(W + (size_t)capg * 1280);
        float4* Ws4 = (float4*)Wsm;
        for (int i = id; i < 1280; i += 256) Ws4[i] = Wg[i];
        float4* us4 = (float4*)usm;
        for (int i = id; i < 512; i += 256) {
            int im = i >> 3, r = i & 7;
            us4[i] = *(const float4*)(g_u + (size_t)(img0 + im) * 9216
                                      + capg * 8 + r * 4);
        }
    }
    __syncthreads();
    for (int it = 0; it < 40; it++) {
        int flat = it * 256 + id;
        int oe4  = flat % 40;
        int cap  = (flat / 40) & 3;
        int im   = flat / 160;
        int o    = oe4 >> 2;
        int e0   = (oe4 & 3) * 4;
        const float*  up = &usm[im * 32 + cap * 8];
        const float4* Wp = (const float4*)&Wsm[cap * 1280 + o * 128 + e0];
        float4 acc = make_float4(0.f, 0.f, 0.f, 0.f);
#pragma unroll
        for (int d = 0; d < 8; d++) {
            float  ud = up[d];
            float4 w4 = Wp[d * 4];
            acc.x = fmaf(ud, w4.x, acc.x);
            acc.y = fmaf(ud, w4.y, acc.y);
            acc.z = fmaf(ud, w4.z, acc.z);
            acc.w = fmaf(ud, w4.w, acc.w);
        }
        __half2 h0 = __floats2half2_rn(acc.x, acc.y);
        __half2 h1 = __floats2half2_rn(acc.z, acc.w);
        uint2 pk = make_uint2(*(uint32_t*)&h0, *(uint32_t*)&h1);
        *(uint2*)&g_uhat_h[((size_t)(img0 + im) * 1152 + capg + cap) * 160
                           + o * 16 + e0] = pk;
    }
}

// ---------------------------------------------------------------------------
// fused routing iteration, smem-staged (unchanged)
// ---------------------------------------------------------------------------
__global__ __launch_bounds__(160) void k_route(int uniform)
{
    __shared__ __align__(16) __half tile[128 * 168];
    __shared__ float vs[160];
    __shared__ float c_sm[128][10];
    const int b     = blockIdx.x;
    const int chunk = blockIdx.y;
    const int tid   = threadIdx.x;
    const __half* ub = g_uhat_h + (size_t)b * 184320 + (size_t)chunk * 128 * 160;

    if (uniform) {
        const int oe = tid;
        float acc = 0.f;
#pragma unroll 4
        for (int cap = 0; cap < 128; cap++)
            acc += __half2float(ub[(size_t)cap * 160 + oe]);
        g_spart[((size_t)chunk * 512 + b) * 160 + oe] = acc * 0.1f;
        return;
    }

    vs[tid] = g_vsum[b * 160 + tid];
    for (int f = tid; f < 2560; f += 160) {
        const int r = f / 20, j = f % 20;
        *(uint4*)&tile[r * 168 + j * 8] = *(const uint4*)(ub + (size_t)r * 160 + j * 8);
    }
    __syncthreads();

    if (tid < 128) {
        const __half2* row = (const __half2*)&tile[tid * 168];
        float t[10];
#pragma unroll
        for (int o = 0; o < 10; o++) {
            float s = 0.f;
#pragma unroll
            for (int e2 = 0; e2 < 8; e2++) {
                float2 f = __half22float2(row[o * 8 + e2]);
                s += f.x * vs[o * 16 + e2 * 2] + f.y * vs[o * 16 + e2 * 2 + 1];
            }
            t[o] = s;
        }
        float m = t[0];
#pragma unroll
        for (int o = 1; o < 10; o++) m = fmaxf(m, t[o]);
        float se = 0.f;
#pragma unroll
        for (int o = 0; o < 10; o++) { t[o] = expf(t[o] - m); se += t[o]; }
        float inv = 1.f / se;
#pragma unroll
        for (int o = 0; o < 10; o++) c_sm[tid][o] = t[o] * inv;
    }
    __syncthreads();

    const int oe = tid;
    const int o  = oe >> 4;
    float acc = 0.f;
#pragma unroll 4
    for (int cap = 0; cap < 128; cap++)
        acc = fmaf(c_sm[cap][o], __half2float(tile[cap * 168 + oe]), acc);
    g_spart[((size_t)chunk * 512 + b) * 160 + oe] = acc;
}

// ---------------------------------------------------------------------------
// sum partials + squash (unchanged)
// ---------------------------------------------------------------------------
__global__ void k_squash_v(float* __restrict__ out, int mode)
{
    int idx = blockIdx.x * 256 + threadIdx.x;
    if (idx >= 5120) return;
    float4 r[4];
#pragma unroll
    for (int i = 0; i < 4; i++) r[i] = make_float4(0.f, 0.f, 0.f, 0.f);
#pragma unroll
    for (int p = 0; p < 9; p++) {
        const float4* sp = (const float4*)(g_spart + (size_t)p * 81920
                                           + (size_t)idx * 16);
#pragma unroll
        for (int i = 0; i < 4; i++) {
            float4 v = sp[i];
            r[i].x += v.x; r[i].y += v.y; r[i].z += v.z; r[i].w += v.w;
        }
    }
    float sn = 0.f;
#pragma unroll
    for (int i = 0; i < 4; i++)
        sn += r[i].x*r[i].x + r[i].y*r[i].y + r[i].z*r[i].z + r[i].w*r[i].w;
    float sc = sn / ((1.f + sn) * (sqrtf(sn) + 1e-6f));
#pragma unroll
    for (int i = 0; i < 4; i++) {
        r[i].x *= sc; r[i].y *= sc; r[i].z *= sc; r[i].w *= sc;
    }
    if (mode == 0) {
        float4* q = (float4*)(g_vsum + (size_t)idx * 16);
#pragma unroll
        for (int i = 0; i < 4; i++) q[i] = r[i];
    } else if (mode == 1) {
        float4* q = (float4*)(g_vsum + (size_t)idx * 16);
#pragma unroll
        for (int i = 0; i < 4; i++) {
            float4 old = q[i];
            old.x += r[i].x; old.y += r[i].y; old.z += r[i].z; old.w += r[i].w;
            q[i] = old;
        }
    } else {
        float4* q = (float4*)(out + (size_t)idx * 16);
#pragma unroll
        for (int i = 0; i < 4; i++) q[i] = r[i];
    }
}

// ---------------------------------------------------------------------------
extern "C" void kernel_launch(void* const* d_in, const int* in_sizes, int n_in,
                              void* d_out, int out_size)
{
    const float* x   = (const float*)d_in[0];
    const float* w1  = (const float*)d_in[1];
    const float* b1  = (const float*)d_in[2];
    const float* w2  = (const float*)d_in[3];
    const float* b2  = (const float*)d_in[4];
    const float* W   = (const float*)d_in[5];
    float* out = (float*)d_out;

    cudaFuncSetAttribute(k_conv1,
                         cudaFuncAttributeMaxDynamicSharedMemorySize, 72512);
    cudaFuncSetAttribute(k_conv2mma,
                         cudaFuncAttributeMaxDynamicSharedMemorySize, 98304);

    k_conv1<<<dim3(512, 8), 256, 72512>>>(x, w1, b1);
    k_wprep<<<256, 256>>>(w2);
    k_conv2mma<<<dim3(72, 2), 512, 98304>>>(b2);
    k_squash_pc<<<2304, 256>>>();
    k_uhat<<<dim3(288, 8), 256>>>(W);

    k_route<<<dim3(512, 9), 160>>>(1);       // iter 0: uniform c
    k_squash_v<<<20, 256>>>(nullptr, 0);     // vsum = v0
    k_route<<<dim3(512, 9), 160>>>(0);       // iter 1
    k_squash_v<<<20, 256>>>(nullptr, 1);     // vsum += v1
    k_route<<<dim3(512, 9), 160>>>(0);       // iter 2
    k_squash_v<<<20, 256>>>(out, 2);         // out = v2
}

// round 10
// speedup vs baseline: 2.4320x; 1.2555x over previous
#include <cuda_runtime.h>
#include <cuda_fp16.h>
#include <cstdint>
#include <math.h>

// ===========================================================================
// CapsNet forward, B=512 — Round 10:
//  conv2: tile M=256 x N=128 (grid 144), A staged via ONE cp.async.bulk per
//  chunk from a pre-swizzled chunk-contiguous w2t layout; B via CP16 (16KB).
//  Staging issue cost drops ~3x -> near tensor-bound.
// ===========================================================================

// ------------------------------ scratch ------------------------------------
__device__ __align__(128) __half g_h1t [512u * 400u * 256u];   // 105 MB NHWC
__device__ __align__(128) __half g_w2t [81u * 4u * 16384u];    // 10.6 MB, chunked+swizzled
__device__ float  g_h2[512u * 9216u];
__device__ float  g_u [512u * 9216u];
__device__ __half g_uhat_h[512u * 1152u * 160u];               // 188.7 MB
__device__ float  g_spart[9u * 512u * 160u];
__device__ float  g_vsum[512u * 160u];

// ------------------------------ PTX helpers --------------------------------
__device__ __forceinline__ uint32_t smem_u32(const void* p) {
    uint32_t a;
    asm("{ .reg .u64 t; cvta.to.shared.u64 t, %1; cvt.u32.u64 %0, t; }"
        : "=r"(a) : "l"(p));
    return a;
}
#define CP16(dst, src) \
    asm volatile("cp.async.cg.shared.global [%0], [%1], 16;" :: "r"(dst), "l"(src) : "memory")
#define CP_COMMIT() asm volatile("cp.async.commit_group;" ::: "memory")
#define CP_WAIT1()  asm volatile("cp.async.wait_group 1;" ::: "memory")
#define CP_WAIT0()  asm volatile("cp.async.wait_group 0;" ::: "memory")

#define MBAR_INIT(a, n) \
    asm volatile("mbarrier.init.shared.b64 [%0], %1;" :: "r"(a), "r"(n) : "memory")
#define MBAR_EXPECT_TX(a, bytes) \
    asm volatile("mbarrier.arrive.expect_tx.shared.b64 _, [%0], %1;" \
                 :: "r"(a), "r"(bytes) : "memory")
#define MBAR_WAIT(a, ph) do {                                                  \
    uint32_t _m = (a), _p = (ph), _d;                                          \
    asm volatile("{ .reg .pred p;"                                             \
        "mbarrier.try_wait.parity.acquire.cta.shared::cta.b64 p, [%1], %2;"    \
        "selp.b32 %0,1,0,p; }" : "=r"(_d) : "r"(_m), "r"(_p) : "memory");      \
    if (!_d) {                                                                 \
        asm volatile("{ .reg .pred P1; WL_%=:"                                 \
            "mbarrier.try_wait.parity.acquire.cta.shared::cta.b64 P1, [%0], %1, 0x989680;" \
            "@P1 bra.uni WD_%=; bra.uni WL_%=; WD_%=: }"                       \
            :: "r"(_m), "r"(_p) : "memory");                                   \
    }                                                                          \
} while (0)
#define BULK_G2S(dst, src, size, mbar) \
    asm volatile("cp.async.bulk.shared::cta.global.mbarrier::complete_tx::bytes " \
                 "[%0], [%1], %2, [%3];" \
                 :: "r"(dst), "l"(src), "r"(size), "r"(mbar) : "memory")

__device__ __forceinline__ void ldsm_x4(uint32_t* r, uint32_t addr) {
    asm volatile("ldmatrix.sync.aligned.m8n8.x4.shared.b16 {%0,%1,%2,%3}, [%4];"
                 : "=r"(r[0]), "=r"(r[1]), "=r"(r[2]), "=r"(r[3]) : "r"(addr));
}
__device__ __forceinline__ void mma16816h(float* c, const uint32_t* a,
                                          const uint32_t* b) {
    asm volatile("mma.sync.aligned.m16n8k16.row.col.f32.f16.f16.f32 "
                 "{%0,%1,%2,%3}, {%4,%5,%6,%7}, {%8,%9}, {%0,%1,%2,%3};"
                 : "+f"(c[0]), "+f"(c[1]), "+f"(c[2]), "+f"(c[3])
                 : "r"(a[0]), "r"(a[1]), "r"(a[2]), "r"(a[3]),
                   "r"(b[0]), "r"(b[1]));
}
__device__ __forceinline__ uint32_t swz(uint32_t o) {
    return o ^ ((o >> 3) & 0x70);
}

// ---------------------------------------------------------------------------
// conv1 + relu -> single fp16 NHWC. grid (512, 8), block 256, 72512 B smem.
// ---------------------------------------------------------------------------
__global__ __launch_bounds__(256) void k_conv1(const float* __restrict__ x,
                                               const float* __restrict__ w1,
                                               const float* __restrict__ b1)
{
    extern __shared__ __align__(16) char c1smem[];
    float* xs = (float*)c1smem;
    float* ws = xs + 2352;
    __half* st = (__half*)(c1smem + 40512);

    const int b  = blockIdx.x;
    const int cg = blockIdx.y;
    const int id = threadIdx.x;
    {
        const float4* xg = (const float4*)(x + b * 2352);
        float4* xs4 = (float4*)xs;
        for (int i = id; i < 588; i += 256) xs4[i] = xg[i];
        const float4* wg = (const float4*)(w1 + cg * 7776);
        float4* ws4 = (float4*)ws;
        for (int i = id; i < 1944; i += 256) ws4[i] = wg[i];
    }
    __syncthreads();
    const int ty = id & 3;
    const int tx = id >> 2;
    float bias[8];
#pragma unroll
    for (int i = 0; i < 8; i++) bias[i] = b1[cg * 32 + ty + 4 * i];

    for (int qi = 0; qi < 2; qi++) {
        int gq = tx + 64 * qi;
        if (gq < 100) {
            int oy  = gq / 5;
            int oxb = (gq % 5) * 4;
            float acc[8][4];
#pragma unroll
            for (int i = 0; i < 8; i++)
#pragma unroll
                for (int j = 0; j < 4; j++) acc[i][j] = 0.f;
            for (int c = 0; c < 3; c++) {
                for (int ky = 0; ky < 9; ky++) {
                    const float* xrow = &xs[(c * 28 + oy + ky) * 28 + oxb];
                    float rin[12];
                    *(float4*)(rin)     = *(const float4*)(xrow);
                    *(float4*)(rin + 4) = *(const float4*)(xrow + 4);
                    *(float4*)(rin + 8) = *(const float4*)(xrow + 8);
                    const int kb = c * 81 + ky * 9;
#pragma unroll
                    for (int kx = 0; kx < 9; kx++) {
#pragma unroll
                        for (int i = 0; i < 8; i++) {
                            float w = ws[(ty + 4 * i) * 243 + kb + kx];
                            acc[i][0] = fmaf(w, rin[kx],     acc[i][0]);
                            acc[i][1] = fmaf(w, rin[kx + 1], acc[i][1]);
                            acc[i][2] = fmaf(w, rin[kx + 2], acc[i][2]);
                            acc[i][3] = fmaf(w, rin[kx + 3], acc[i][3]);
                        }
                    }
                }
            }
#pragma unroll
            for (int i = 0; i < 8; i++) {
                const int ch = ty + 4 * i;
#pragma unroll
                for (int j = 0; j < 4; j++) {
                    const int pix = gq * 4 + j;
                    st[pix * 40 + ch] =
                        __float2half(fmaxf(acc[i][j] + bias[i], 0.f));
                }
            }
        }
    }
    __syncthreads();

    for (int f = id; f < 1600; f += 256) {
        const int pix = f >> 2;
        const int j   = f & 3;
        const size_t dst = ((size_t)b * 400 + pix) * 256 + cg * 32 + j * 8;
        *(uint4*)&g_h1t[dst] = *(const uint4*)&st[pix * 40 + j * 8];
    }
}

// ---------------------------------------------------------------------------
// W2 [co][c][9][9] -> chunk-contiguous pre-swizzled fp16:
// g_w2t[(kk*4+cq)*16384 + swz(co*128 + c64*2)/2]. grid 256, block 256.
// ---------------------------------------------------------------------------
__global__ __launch_bounds__(256) void k_wprep(const float* __restrict__ w2)
{
    __shared__ float wt[128 * 81];
    const int co  = blockIdx.x;
    const int id  = threadIdx.x;
    const int c   = id & 127;
    const int hf  = id >> 7;

    for (int cc = 0; cc < 2; cc++) {
        __syncthreads();
        const float* src = w2 + (size_t)co * 20736 + cc * 128 * 81;
        for (int i = id; i < 128 * 81; i += 256) wt[i] = src[i];
        __syncthreads();
        const int cglob = cc * 128 + c;
        const int cq    = cglob >> 6;
        const int c64   = cglob & 63;
        const uint32_t inner = swz((uint32_t)co * 128 + c64 * 2) >> 1;
        const int k0 = hf ? 41 : 0;
        const int k1 = hf ? 81 : 41;
        for (int kk = k0; kk < k1; kk++) {
            g_w2t[(size_t)(kk * 4 + cq) * 16384 + inner] =
                __float2half(wt[c * 81 + kk]);
        }
    }
}

// ---------------------------------------------------------------------------
// conv2 implicit GEMM. grid (144), block 512, dyn smem 98336 B.
// CTA tile M=256 co x N=128 pos; 324 K64 chunks (81 taps x 4 cq).
// A: one cp.async.bulk of 32KB/chunk (pre-swizzled). B: 1024 CP16 (16KB).
// Warps 4(M: 64 co) x 4(N: 32 pos); warp tile 64x32, acc 4x4x4.
// ---------------------------------------------------------------------------
#define STAGE_BYTES 49152
#define A_BYTES 32768
#define B_OFF 32768
#define MB_OFF 98304
#define NCHUNK 324

__global__ __launch_bounds__(512) void k_conv2mma(const float* __restrict__ b2)
{
    extern __shared__ __align__(1024) char dynsmem[];
    const uint32_t sb = smem_u32(dynsmem);
    const int tid  = threadIdx.x;
    const int warp = tid >> 5;
    const int lane = tid & 31;
    const int n0    = blockIdx.x * 128;
    const int mwarp = warp & 3;       // co: mwarp*64
    const int nwarp = warp >> 2;      // n : nwarp*32

    if (tid == 0) {
        MBAR_INIT(sb + MB_OFF, 1);
        MBAR_INIT(sb + MB_OFF + 8, 1);
    }
    __syncthreads();

    // B loader: each thread handles rows r = tid>>3 and r+64, u = tid&7
    const int uB = tid & 7;
    int pixBase[2];
#pragma unroll
    for (int h = 0; h < 2; h++) {
        const int n    = n0 + (tid >> 3) + h * 64;
        const int bimg = n / 36;
        const int pos  = n - bimg * 36;
        const int oy   = pos / 6, ox = pos - oy * 6;
        pixBase[h] = (bimg * 400 + oy * 40 + ox * 2) * 256 + uB * 8;
    }
    uint32_t bDst[2];
    bDst[0] = swz((uint32_t)(tid >> 3) * 128 + uB * 16);
    bDst[1] = swz(((uint32_t)(tid >> 3) + 64) * 128 + uB * 16);

    // ldmatrix lane addressing
    const int aRowSub = lane & 15;
    const int aColSel = (lane >> 4) * 16;
    const int bMat    = lane >> 3;
    const int bSub    = lane & 7;
    const int bNfSel  = bMat >> 1;
    const int bKSel   = (bMat & 1) * 16;

    float acc[4][4][4];
#pragma unroll
    for (int mf = 0; mf < 4; mf++)
#pragma unroll
        for (int nf = 0; nf < 4; nf++)
#pragma unroll
            for (int i = 0; i < 4; i++) acc[mf][nf][i] = 0.f;

    // ---- prologue: chunk 0 into stage 0
    if (tid == 0) {
        MBAR_EXPECT_TX(sb + MB_OFF, A_BYTES);
        BULK_G2S(sb, (const char*)g_w2t, A_BYTES, sb + MB_OFF);
    }
    {
        const int tap = 0, cOff = 0;
#pragma unroll
        for (int h = 0; h < 2; h++)
            CP16(sb + B_OFF + bDst[h], g_h1t + pixBase[h] + tap + cOff);
    }
    CP_COMMIT();

    for (int t = 0; t < NCHUNK; t++) {
        const int s = t & 1, s2 = s ^ 1;
        if (t + 1 < NCHUNK) {
            const int tn = t + 1;
            const int kk = tn >> 2, cq = tn & 3;
            if (tid == 0) {
                MBAR_EXPECT_TX(sb + MB_OFF + 8 * s2, A_BYTES);
                BULK_G2S(sb + s2 * STAGE_BYTES,
                         (const char*)(g_w2t + (size_t)tn * 16384),
                         A_BYTES, sb + MB_OFF + 8 * s2);
            }
            const int ky = kk / 9, kx = kk - ky * 9;
            const int tap  = (ky * 20 + kx) * 256;
            const int cOff = cq * 64;
#pragma unroll
            for (int h = 0; h < 2; h++)
                CP16(sb + s2 * STAGE_BYTES + B_OFF + bDst[h],
                     g_h1t + pixBase[h] + tap + cOff);
            CP_COMMIT();
            CP_WAIT1();
        } else {
            CP_WAIT0();
        }
        MBAR_WAIT(sb + MB_OFF + 8 * s, (t >> 1) & 1);
        __syncthreads();

        const uint32_t stb = sb + s * STAGE_BYTES;
        const uint32_t aa = stb;
        const uint32_t bb = stb + B_OFF;

#pragma unroll
        for (int q = 0; q < 4; q++) {
            const int qb = q * 32;
            uint32_t B[4][2];
#pragma unroll
            for (int gp = 0; gp < 2; gp++) {
                uint32_t off = swz((nwarp * 32 + (gp * 2 + bNfSel) * 8 + bSub) * 128
                                   + qb + bKSel);
                uint32_t r[4];
                ldsm_x4(r, bb + off);
                B[gp*2][0] = r[0]; B[gp*2][1] = r[1];
                B[gp*2+1][0] = r[2]; B[gp*2+1][1] = r[3];
            }
#pragma unroll
            for (int mf = 0; mf < 4; mf++) {
                uint32_t A[4];
                uint32_t offA = swz((mwarp * 64 + mf * 16 + aRowSub) * 128
                                    + qb + aColSel);
                ldsm_x4(A, aa + offA);
#pragma unroll
                for (int nf = 0; nf < 4; nf++)
                    mma16816h(acc[mf][nf], A, B[nf]);
            }
        }
        __syncthreads();
    }

    // epilogue: bias + store to h2 [b][co][pos]
#pragma unroll
    for (int mf = 0; mf < 4; mf++) {
        const int coB = mwarp * 64 + mf * 16 + (lane >> 2);
        const float bias0 = b2[coB];
        const float bias1 = b2[coB + 8];
#pragma unroll
        for (int nf = 0; nf < 4; nf++) {
#pragma unroll
            for (int i = 0; i < 4; i++) {
                const int co = coB + ((i >> 1) << 3);
                const int n  = n0 + nwarp * 32 + nf * 8 + ((lane & 3) << 1) + (i & 1);
                const int bi = n / 36;
                const int pp = n - bi * 36;
                g_h2[(size_t)bi * 9216 + co * 36 + pp] =
                    acc[mf][nf][i] + ((i >> 1) ? bias1 : bias0);
            }
        }
    }
}

// ---------------------------------------------------------------------------
// primary capsule squash (unchanged)
// ---------------------------------------------------------------------------
__global__ __launch_bounds__(256) void k_squash_pc()
{
    unsigned idx = blockIdx.x * 256u + threadIdx.x;
    if (idx >= 589824u) return;
    const float4* p = (const float4*)(g_h2 + (size_t)idx * 8);
    float4 a = p[0], b = p[1];
    float sn = a.x*a.x + a.y*a.y + a.z*a.z + a.w*a.w
             + b.x*b.x + b.y*b.y + b.z*b.z + b.w*b.w;
    float sc = sn / ((1.f + sn) * (sqrtf(sn) + 1e-6f));
    a.x *= sc; a.y *= sc; a.z *= sc; a.w *= sc;
    b.x *= sc; b.y *= sc; b.z *= sc; b.w *= sc;
    float4* q = (float4*)(g_u + (size_t)idx * 8);
    q[0] = a; q[1] = b;
}

// ---------------------------------------------------------------------------
// u_hat -> fp16 (unchanged)
// ---------------------------------------------------------------------------
__global__ __launch_bounds__(256) void k_uhat(const float* __restrict__ W)
{
    __shared__ float Wsm[4 * 1280];
    __shared__ float usm[64 * 32];
    const int capg = blockIdx.x * 4;
    const int img0 = blockIdx.y * 64;
    const int id   = threadIdx.x;
    {
        const float4* Wg = (const float4*)(W + (size_t)capg * 1280);
        float4* Ws4 = (float4*)Wsm;
        for (int i = id; i < 1280; i += 256) Ws4[i] = Wg[i];
        float4* us4 = (float4*)usm;
        for (int i = id; i < 512; i += 256) {
            int im = i >> 3, r = i & 7;
            us4[i] = *(const float4*)(g_u + (size_t)(img0 + im) * 9216
                                      + capg * 8 + r * 4);
        }
    }
    __syncthreads();
    for (int it = 0; it < 40; it++) {
        int flat = it * 256 + id;
        int oe4  = flat % 40;
        int cap  = (flat / 40) & 3;
        int im   = flat / 160;
        int o    = oe4 >> 2;
        int e0   = (oe4 & 3) * 4;
        const float*  up = &usm[im * 32 + cap * 8];
        const float4* Wp = (const float4*)&Wsm[cap * 1280 + o * 128 + e0];
        float4 acc = make_float4(0.f, 0.f, 0.f, 0.f);
#pragma unroll
        for (int d = 0; d < 8; d++) {
            float  ud = up[d];
            float4 w4 = Wp[d * 4];
            acc.x = fmaf(ud, w4.x, acc.x);
            acc.y = fmaf(ud, w4.y, acc.y);
            acc.z = fmaf(ud, w4.z, acc.z);
            acc.w = fmaf(ud, w4.w, acc.w);
        }
        __half2 h0 = __floats2half2_rn(acc.x, acc.y);
        __half2 h1 = __floats2half2_rn(acc.z, acc.w);
        uint2 pk = make_uint2(*(uint32_t*)&h0, *(uint32_t*)&h1);
        *(uint2*)&g_uhat_h[((size_t)(img0 + im) * 1152 + capg + cap) * 160
                           + o * 16 + e0] = pk;
    }
}

// ---------------------------------------------------------------------------
// fused routing iteration, smem-staged (unchanged)
// ---------------------------------------------------------------------------
__global__ __launch_bounds__(160) void k_route(int uniform)
{
    __shared__ __align__(16) __half tile[128 * 168];
    __shared__ float vs[160];
    __shared__ float c_sm[128][10];
    const int b     = blockIdx.x;
    const int chunk = blockIdx.y;
    const int tid   = threadIdx.x;
    const __half* ub = g_uhat_h + (size_t)b * 184320 + (size_t)chunk * 128 * 160;

    if (uniform) {
        const int oe = tid;
        float acc = 0.f;
#pragma unroll 4
        for (int cap = 0; cap < 128; cap++)
            acc += __half2float(ub[(size_t)cap * 160 + oe]);
        g_spart[((size_t)chunk * 512 + b) * 160 + oe] = acc * 0.1f;
        return;
    }

    vs[tid] = g_vsum[b * 160 + tid];
    for (int f = tid; f < 2560; f += 160) {
        const int r = f / 20, j = f % 20;
        *(uint4*)&tile[r * 168 + j * 8] = *(const uint4*)(ub + (size_t)r * 160 + j * 8);
    }
    __syncthreads();

    if (tid < 128) {
        const __half2* row = (const __half2*)&tile[tid * 168];
        float t[10];
#pragma unroll
        for (int o = 0; o < 10; o++) {
            float s = 0.f;
#pragma unroll
            for (int e2 = 0; e2 < 8; e2++) {
                float2 f = __half22float2(row[o * 8 + e2]);
                s += f.x * vs[o * 16 + e2 * 2] + f.y * vs[o * 16 + e2 * 2 + 1];
            }
            t[o] = s;
        }
        float m = t[0];
#pragma unroll
        for (int o = 1; o < 10; o++) m = fmaxf(m, t[o]);
        float se = 0.f;
#pragma unroll
        for (int o = 0; o < 10; o++) { t[o] = expf(t[o] - m); se += t[o]; }
        float inv = 1.f / se;
#pragma unroll
        for (int o = 0; o < 10; o++) c_sm[tid][o] = t[o] * inv;
    }
    __syncthreads();

    const int oe = tid;
    const int o  = oe >> 4;
    float acc = 0.f;
#pragma unroll 4
    for (int cap = 0; cap < 128; cap++)
        acc = fmaf(c_sm[cap][o], __half2float(tile[cap * 168 + oe]), acc);
    g_spart[((size_t)chunk * 512 + b) * 160 + oe] = acc;
}

// ---------------------------------------------------------------------------
// sum partials + squash (unchanged)
// ---------------------------------------------------------------------------
__global__ void k_squash_v(float* __restrict__ out, int mode)
{
    int idx = blockIdx.x * 256 + threadIdx.x;
    if (idx >= 5120) return;
    float4 r[4];
#pragma unroll
    for (int i = 0; i < 4; i++) r[i] = make_float4(0.f, 0.f, 0.f, 0.f);
#pragma unroll
    for (int p = 0; p < 9; p++) {
        const float4* sp = (const float4*)(g_spart + (size_t)p * 81920
                                           + (size_t)idx * 16);
#pragma unroll
        for (int i = 0; i < 4; i++) {
            float4 v = sp[i];
            r[i].x += v.x; r[i].y += v.y; r[i].z += v.z; r[i].w += v.w;
        }
    }
    float sn = 0.f;
#pragma unroll
    for (int i = 0; i < 4; i++)
        sn += r[i].x*r[i].x + r[i].y*r[i].y + r[i].z*r[i].z + r[i].w*r[i].w;
    float sc = sn / ((1.f + sn) * (sqrtf(sn) + 1e-6f));
#pragma unroll
    for (int i = 0; i < 4; i++) {
        r[i].x *= sc; r[i].y *= sc; r[i].z *= sc; r[i].w *= sc;
    }
    if (mode == 0) {
        float4* q = (float4*)(g_vsum + (size_t)idx * 16);
#pragma unroll
        for (int i = 0; i < 4; i++) q[i] = r[i];
    } else if (mode == 1) {
        float4* q = (float4*)(g_vsum + (size_t)idx * 16);
#pragma unroll
        for (int i = 0; i < 4; i++) {
            float4 old = q[i];
            old.x += r[i].x; old.y += r[i].y; old.z += r[i].z; old.w += r[i].w;
            q[i] = old;
        }
    } else {
        float4* q = (float4*)(out + (size_t)idx * 16);
#pragma unroll
        for (int i = 0; i < 4; i++) q[i] = r[i];
    }
}

// ---------------------------------------------------------------------------
extern "C" void kernel_launch(void* const* d_in, const int* in_sizes, int n_in,
                              void* d_out, int out_size)
{
    const float* x   = (const float*)d_in[0];
    const float* w1  = (const float*)d_in[1];
    const float* b1  = (const float*)d_in[2];
    const float* w2  = (const float*)d_in[3];
    const float* b2  = (const float*)d_in[4];
    const float* W   = (const float*)d_in[5];
    float* out = (float*)d_out;

    cudaFuncSetAttribute(k_conv1,
                         cudaFuncAttributeMaxDynamicSharedMemorySize, 72512);
    cudaFuncSetAttribute(k_conv2mma,
                         cudaFuncAttributeMaxDynamicSharedMemorySize, 98336);

    k_conv1<<<dim3(512, 8), 256, 72512>>>(x, w1, b1);
    k_wprep<<<256, 256>>>(w2);
    k_conv2mma<<<144, 512, 98336>>>(b2);
    k_squash_pc<<<2304, 256>>>();
    k_uhat<<<dim3(288, 8), 256>>>(W);

    k_route<<<dim3(512, 9), 160>>>(1);       // iter 0: uniform c
    k_squash_v<<<20, 256>>>(nullptr, 0);     // vsum = v0
    k_route<<<dim3(512, 9), 160>>>(0);       // iter 1
    k_squash_v<<<20, 256>>>(nullptr, 1);     // vsum += v1
    k_route<<<dim3(512, 9), 160>>>(0);       // iter 2
    k_squash_v<<<20, 256>>>(out, 2);         // out = v2
}

// round 11
// speedup vs baseline: 3.0575x; 1.2572x over previous
#include <cuda_runtime.h>
#include <cuda_fp16.h>
#include <cstdint>
#include <math.h>

// ===========================================================================
// CapsNet forward, B=512 — Round 11: conv1 moved to tensor cores.
//   k_im2col  : x -> x2col[204800][256] fp16 (K=243 padded to 256)
//   k_w1prep  : w1 -> chunk-contiguous pre-swizzled fp16 hi|lo (2-term exact)
//   k_conv1mma: R10-style pipeline, M=256 co x N=128 pos, 4 K64 chunks,
//               bulk A (64KB/chunk), CP16 B, epilogue relu+fp16 -> h1t
//   conv2 / routing unchanged from Round 10.
// ===========================================================================

// ------------------------------ scratch ------------------------------------
__device__ __align__(128) __half g_x2col[512u * 400u * 256u];  // 105 MB
__device__ __align__(128) __half g_w1t [4u * 32768u];          // 256 KB hi|lo per chunk
__device__ __align__(128) __half g_h1t [512u * 400u * 256u];   // 105 MB NHWC
__device__ __align__(128) __half g_w2t [81u * 4u * 16384u];    // 10.6 MB
__device__ float  g_h2[512u * 9216u];
__device__ float  g_u [512u * 9216u];
__device__ __half g_uhat_h[512u * 1152u * 160u];               // 188.7 MB
__device__ float  g_spart[9u * 512u * 160u];
__device__ float  g_vsum[512u * 160u];

// ------------------------------ PTX helpers --------------------------------
__device__ __forceinline__ uint32_t smem_u32(const void* p) {
    uint32_t a;
    asm("{ .reg .u64 t; cvta.to.shared.u64 t, %1; cvt.u32.u64 %0, t; }"
        : "=r"(a) : "l"(p));
    return a;
}
#define CP16(dst, src) \
    asm volatile("cp.async.cg.shared.global [%0], [%1], 16;" :: "r"(dst), "l"(src) : "memory")
#define CP_COMMIT() asm volatile("cp.async.commit_group;" ::: "memory")
#define CP_WAIT1()  asm volatile("cp.async.wait_group 1;" ::: "memory")
#define CP_WAIT0()  asm volatile("cp.async.wait_group 0;" ::: "memory")

#define MBAR_INIT(a, n) \
    asm volatile("mbarrier.init.shared.b64 [%0], %1;" :: "r"(a), "r"(n) : "memory")
#define MBAR_EXPECT_TX(a, bytes) \
    asm volatile("mbarrier.arrive.expect_tx.shared.b64 _, [%0], %1;" \
                 :: "r"(a), "r"(bytes) : "memory")
#define MBAR_WAIT(a, ph) do {                                                  \
    uint32_t _m = (a), _p = (ph), _d;                                          \
    asm volatile("{ .reg .pred p;"                                             \
        "mbarrier.try_wait.parity.acquire.cta.shared::cta.b64 p, [%1], %2;"    \
        "selp.b32 %0,1,0,p; }" : "=r"(_d) : "r"(_m), "r"(_p) : "memory");      \
    if (!_d) {                                                                 \
        asm volatile("{ .reg .pred P1; WL_%=:"                                 \
            "mbarrier.try_wait.parity.acquire.cta.shared::cta.b64 P1, [%0], %1, 0x989680;" \
            "@P1 bra.uni WD_%=; bra.uni WL_%=; WD_%=: }"                       \
            :: "r"(_m), "r"(_p) : "memory");                                   \
    }                                                                          \
} while (0)
#define BULK_G2S(dst, src, size, mbar) \
    asm volatile("cp.async.bulk.shared::cta.global.mbarrier::complete_tx::bytes " \
                 "[%0], [%1], %2, [%3];" \
                 :: "r"(dst), "l"(src), "r"(size), "r"(mbar) : "memory")

__device__ __forceinline__ void ldsm_x4(uint32_t* r, uint32_t addr) {
    asm volatile("ldmatrix.sync.aligned.m8n8.x4.shared.b16 {%0,%1,%2,%3}, [%4];"
                 : "=r"(r[0]), "=r"(r[1]), "=r"(r[2]), "=r"(r[3]) : "r"(addr));
}
__device__ __forceinline__ void mma16816h(float* c, const uint32_t* a,
                                          const uint32_t* b) {
    asm volatile("mma.sync.aligned.m16n8k16.row.col.f32.f16.f16.f32 "
                 "{%0,%1,%2,%3}, {%4,%5,%6,%7}, {%8,%9}, {%0,%1,%2,%3};"
                 : "+f"(c[0]), "+f"(c[1]), "+f"(c[2]), "+f"(c[3])
                 : "r"(a[0]), "r"(a[1]), "r"(a[2]), "r"(a[3]),
                   "r"(b[0]), "r"(b[1]));
}
__device__ __forceinline__ uint32_t swz(uint32_t o) {
    return o ^ ((o >> 3) & 0x70);
}

// ---------------------------------------------------------------------------
// im2col: x[b][3][28][28] -> x2col[b*400+pos][256] fp16 (k = c*81+ky*9+kx).
// grid 512, block 256. Warp handles one position; lane writes 8 k (uint4).
// ---------------------------------------------------------------------------
__global__ __launch_bounds__(256) void k_im2col(const float* __restrict__ x)
{
    __shared__ float xs[2352];
    __shared__ int   lut[256];
    const int b    = blockIdx.x;
    const int tid  = threadIdx.x;
    const int warp = tid >> 5;
    const int lane = tid & 31;
    {
        const float4* xg = (const float4*)(x + b * 2352);
        float4* xs4 = (float4*)xs;
        for (int i = tid; i < 588; i += 256) xs4[i] = xg[i];
        if (tid < 256) {
            int k = tid;
            if (k < 243) {
                int c = k / 81, kk = k - c * 81;
                int ky = kk / 9, kx = kk - ky * 9;
                lut[k] = c * 784 + ky * 28 + kx;
            } else lut[k] = -1;
        }
    }
    __syncthreads();

    for (int p = warp; p < 400; p += 8) {
        const int oy = p / 20, ox = p - (p / 20) * 20;
        const int off = oy * 28 + ox;
        __align__(16) __half vals[8];
#pragma unroll
        for (int j = 0; j < 8; j++) {
            const int l = lut[lane * 8 + j];
            vals[j] = (l >= 0) ? __float2half(xs[l + off]) : __half(0.f);
        }
        *(uint4*)&g_x2col[((size_t)b * 400 + p) * 256 + lane * 8] =
            *(const uint4*)vals;
    }
}

// ---------------------------------------------------------------------------
// w1[co][3][9][9] -> g_w1t chunked pre-swizzled hi|lo. grid 256, block 256.
// ---------------------------------------------------------------------------
__global__ __launch_bounds__(256) void k_w1prep(const float* __restrict__ w1)
{
    const int co = blockIdx.x;
    const int k  = threadIdx.x;
    float v = (k < 243) ? w1[co * 243 + k] : 0.f;
    __half h = __float2half(v);
    __half l = __float2half(v - __half2float(h));
    const int cq  = k >> 6;
    const int k64 = k & 63;
    const uint32_t inner = swz((uint32_t)co * 128 + k64 * 2) >> 1;
    g_w1t[cq * 32768 + inner]         = h;
    g_w1t[cq * 32768 + 16384 + inner] = l;
}

// ---------------------------------------------------------------------------
// conv1 GEMM: h1t[n][co] = relu(sum_k w1[co][k]*x2col[n][k] + b1[co]).
// grid 1600, block 512, dyn smem 163872 B.
// Stage 80KB: Ah[32K]|Al[32K]|B[16K]; 2 stages; 4 K64 chunks; bulk A 64KB.
// ---------------------------------------------------------------------------
#define C1_STAGE 81920
#define C1_B_OFF 65536
#define C1_MB    163840
#define C1_NCH   4

__global__ __launch_bounds__(512) void k_conv1mma(const float* __restrict__ b1)
{
    extern __shared__ __align__(1024) char dynsmem[];
    const uint32_t sb = smem_u32(dynsmem);
    const int tid  = threadIdx.x;
    const int warp = tid >> 5;
    const int lane = tid & 31;
    const int n0    = blockIdx.x * 128;
    const int mwarp = warp & 3;       // co: mwarp*64
    const int nwarp = warp >> 2;      // n : nwarp*32

    if (tid == 0) {
        MBAR_INIT(sb + C1_MB, 1);
        MBAR_INIT(sb + C1_MB + 8, 1);
    }
    __syncthreads();

    // B loader: rows tid>>3 and +64, u = tid&7
    const int uB = tid & 7;
    const int row0 = tid >> 3;
    const uint32_t pixBase0 = (uint32_t)(n0 + row0) * 256u + uB * 8;
    const uint32_t pixBase1 = (uint32_t)(n0 + row0 + 64) * 256u + uB * 8;
    const uint32_t bDst0 = swz((uint32_t)row0 * 128 + uB * 16);
    const uint32_t bDst1 = swz(((uint32_t)row0 + 64) * 128 + uB * 16);

    const int aRowSub = lane & 15;
    const int aColSel = (lane >> 4) * 16;
    const int bMat    = lane >> 3;
    const int bSub    = lane & 7;
    const int bNfSel  = bMat >> 1;
    const int bKSel   = (bMat & 1) * 16;

    float acc[4][4][4];
#pragma unroll
    for (int mf = 0; mf < 4; mf++)
#pragma unroll
        for (int nf = 0; nf < 4; nf++)
#pragma unroll
            for (int i = 0; i < 4; i++) acc[mf][nf][i] = 0.f;

    // prologue: chunk 0 -> stage 0
    if (tid == 0) {
        MBAR_EXPECT_TX(sb + C1_MB, 65536);
        BULK_G2S(sb, (const char*)g_w1t, 65536, sb + C1_MB);
    }
    CP16(sb + C1_B_OFF + bDst0, g_x2col + pixBase0);
    CP16(sb + C1_B_OFF + bDst1, g_x2col + pixBase1);
    CP_COMMIT();

    for (int t = 0; t < C1_NCH; t++) {
        const int s = t & 1, s2 = s ^ 1;
        if (t + 1 < C1_NCH) {
            const int tn = t + 1;
            if (tid == 0) {
                MBAR_EXPECT_TX(sb + C1_MB + 8 * s2, 65536);
                BULK_G2S(sb + s2 * C1_STAGE,
                         (const char*)(g_w1t + (size_t)tn * 32768),
                         65536, sb + C1_MB + 8 * s2);
            }
            const int cOff = tn * 64;
            CP16(sb + s2 * C1_STAGE + C1_B_OFF + bDst0, g_x2col + pixBase0 + cOff);
            CP16(sb + s2 * C1_STAGE + C1_B_OFF + bDst1, g_x2col + pixBase1 + cOff);
            CP_COMMIT();
            CP_WAIT1();
        } else {
            CP_WAIT0();
        }
        MBAR_WAIT(sb + C1_MB + 8 * s, (t >> 1) & 1);
        __syncthreads();

        const uint32_t stb = sb + s * C1_STAGE;
        const uint32_t ah = stb, al = stb + 32768;
        const uint32_t bb = stb + C1_B_OFF;

#pragma unroll
        for (int q = 0; q < 4; q++) {
            const int qb = q * 32;
            uint32_t B[4][2];
#pragma unroll
            for (int gp = 0; gp < 2; gp++) {
                uint32_t off = swz((nwarp * 32 + (gp * 2 + bNfSel) * 8 + bSub) * 128
                                   + qb + bKSel);
                uint32_t r[4];
                ldsm_x4(r, bb + off);
                B[gp*2][0] = r[0]; B[gp*2][1] = r[1];
                B[gp*2+1][0] = r[2]; B[gp*2+1][1] = r[3];
            }
#pragma unroll
            for (int mf = 0; mf < 4; mf++) {
                uint32_t Ah[4], Al[4];
                uint32_t offA = swz((mwarp * 64 + mf * 16 + aRowSub) * 128
                                    + qb + aColSel);
                ldsm_x4(Ah, ah + offA);
                ldsm_x4(Al, al + offA);
#pragma unroll
                for (int nf = 0; nf < 4; nf++) {
                    mma16816h(acc[mf][nf], Ah, B[nf]);
                    mma16816h(acc[mf][nf], Al, B[nf]);
                }
            }
        }
        __syncthreads();
    }

    // epilogue: bias + relu + fp16 via smem transpose -> coalesced h1t rows
    __half* ebuf = (__half*)dynsmem;
#pragma unroll
    for (int mf = 0; mf < 4; mf++) {
        const int coB = mwarp * 64 + mf * 16 + (lane >> 2);
        const float bias0 = b1[coB];
        const float bias1 = b1[coB + 8];
#pragma unroll
        for (int nf = 0; nf < 4; nf++) {
#pragma unroll
            for (int i = 0; i < 4; i++) {
                const int co = coB + ((i >> 1) << 3);
                const int nl = nwarp * 32 + nf * 8 + ((lane & 3) << 1) + (i & 1);
                const float v = acc[mf][nf][i] + ((i >> 1) ? bias1 : bias0);
                ebuf[nl * 256 + co] = __float2half(fmaxf(v, 0.f));
            }
        }
    }
    __syncthreads();
    for (int f = tid; f < 128 * 32; f += 512) {
        const int rw = f >> 5;
        const int j  = f & 31;
        *(uint4*)&g_h1t[(size_t)(n0 + rw) * 256 + j * 8] =
            *(const uint4*)&ebuf[rw * 256 + j * 8];
    }
}

// ---------------------------------------------------------------------------
// W2 [co][c][9][9] -> chunk-contiguous pre-swizzled fp16 (unchanged R10).
// ---------------------------------------------------------------------------
__global__ __launch_bounds__(256) void k_wprep(const float* __restrict__ w2)
{
    __shared__ float wt[128 * 81];
    const int co  = blockIdx.x;
    const int id  = threadIdx.x;
    const int c   = id & 127;
    const int hf  = id >> 7;

    for (int cc = 0; cc < 2; cc++) {
        __syncthreads();
        const float* src = w2 + (size_t)co * 20736 + cc * 128 * 81;
        for (int i = id; i < 128 * 81; i += 256) wt[i] = src[i];
        __syncthreads();
        const int cglob = cc * 128 + c;
        const int cq    = cglob >> 6;
        const int c64   = cglob & 63;
        const uint32_t inner = swz((uint32_t)co * 128 + c64 * 2) >> 1;
        const int k0 = hf ? 41 : 0;
        const int k1 = hf ? 81 : 41;
        for (int kk = k0; kk < k1; kk++) {
            g_w2t[(size_t)(kk * 4 + cq) * 16384 + inner] =
                __float2half(wt[c * 81 + kk]);
        }
    }
}

// ---------------------------------------------------------------------------
// conv2 implicit GEMM (unchanged R10). grid 144, block 512, 98336 B smem.
// ---------------------------------------------------------------------------
#define STAGE_BYTES 49152
#define A_BYTES 32768
#define B_OFF 32768
#define MB_OFF 98304
#define NCHUNK 324

__global__ __launch_bounds__(512) void k_conv2mma(const float* __restrict__ b2)
{
    extern __shared__ __align__(1024) char dynsmem[];
    const uint32_t sb = smem_u32(dynsmem);
    const int tid  = threadIdx.x;
    const int warp = tid >> 5;
    const int lane = tid & 31;
    const int n0    = blockIdx.x * 128;
    const int mwarp = warp & 3;
    const int nwarp = warp >> 2;

    if (tid == 0) {
        MBAR_INIT(sb + MB_OFF, 1);
        MBAR_INIT(sb + MB_OFF + 8, 1);
    }
    __syncthreads();

    const int uB = tid & 7;
    int pixBase[2];
#pragma unroll
    for (int h = 0; h < 2; h++) {
        const int n    = n0 + (tid >> 3) + h * 64;
        const int bimg = n / 36;
        const int pos  = n - bimg * 36;
        const int oy   = pos / 6, ox = pos - oy * 6;
        pixBase[h] = (bimg * 400 + oy * 40 + ox * 2) * 256 + uB * 8;
    }
    uint32_t bDst[2];
    bDst[0] = swz((uint32_t)(tid >> 3) * 128 + uB * 16);
    bDst[1] = swz(((uint32_t)(tid >> 3) + 64) * 128 + uB * 16);

    const int aRowSub = lane & 15;
    const int aColSel = (lane >> 4) * 16;
    const int bMat    = lane >> 3;
    const int bSub    = lane & 7;
    const int bNfSel  = bMat >> 1;
    const int bKSel   = (bMat & 1) * 16;

    float acc[4][4][4];
#pragma unroll
    for (int mf = 0; mf < 4; mf++)
#pragma unroll
        for (int nf = 0; nf < 4; nf++)
#pragma unroll
            for (int i = 0; i < 4; i++) acc[mf][nf][i] = 0.f;

    if (tid == 0) {
        MBAR_EXPECT_TX(sb + MB_OFF, A_BYTES);
        BULK_G2S(sb, (const char*)g_w2t, A_BYTES, sb + MB_OFF);
    }
#pragma unroll
    for (int h = 0; h < 2; h++)
        CP16(sb + B_OFF + bDst[h], g_h1t + pixBase[h]);
    CP_COMMIT();

    for (int t = 0; t < NCHUNK; t++) {
        const int s = t & 1, s2 = s ^ 1;
        if (t + 1 < NCHUNK) {
            const int tn = t + 1;
            const int kk = tn >> 2, cq = tn & 3;
            if (tid == 0) {
                MBAR_EXPECT_TX(sb + MB_OFF + 8 * s2, A_BYTES);
                BULK_G2S(sb + s2 * STAGE_BYTES,
                         (const char*)(g_w2t + (size_t)tn * 16384),
                         A_BYTES, sb + MB_OFF + 8 * s2);
            }
            const int ky = kk / 9, kx = kk - ky * 9;
            const int tap  = (ky * 20 + kx) * 256;
            const int cOff = cq * 64;
#pragma unroll
            for (int h = 0; h < 2; h++)
                CP16(sb + s2 * STAGE_BYTES + B_OFF + bDst[h],
                     g_h1t + pixBase[h] + tap + cOff);
            CP_COMMIT();
            CP_WAIT1();
        } else {
            CP_WAIT0();
        }
        MBAR_WAIT(sb + MB_OFF + 8 * s, (t >> 1) & 1);
        __syncthreads();

        const uint32_t stb = sb + s * STAGE_BYTES;
        const uint32_t aa = stb;
        const uint32_t bb = stb + B_OFF;

#pragma unroll
        for (int q = 0; q < 4; q++) {
            const int qb = q * 32;
            uint32_t B[4][2];
#pragma unroll
            for (int gp = 0; gp < 2; gp++) {
                uint32_t off = swz((nwarp * 32 + (gp * 2 + bNfSel) * 8 + bSub) * 128
                                   + qb + bKSel);
                uint32_t r[4];
                ldsm_x4(r, bb + off);
                B[gp*2][0] = r[0]; B[gp*2][1] = r[1];
                B[gp*2+1][0] = r[2]; B[gp*2+1][1] = r[3];
            }
#pragma unroll
            for (int mf = 0; mf < 4; mf++) {
                uint32_t A[4];
                uint32_t offA = swz((mwarp * 64 + mf * 16 + aRowSub) * 128
                                    + qb + aColSel);
                ldsm_x4(A, aa + offA);
#pragma unroll
                for (int nf = 0; nf < 4; nf++)
                    mma16816h(acc[mf][nf], A, B[nf]);
            }
        }
        __syncthreads();
    }

#pragma unroll
    for (int mf = 0; mf < 4; mf++) {
        const int coB = mwarp * 64 + mf * 16 + (lane >> 2);
        const float bias0 = b2[coB];
        const float bias1 = b2[coB + 8];
#pragma unroll
        for (int nf = 0; nf < 4; nf++) {
#pragma unroll
            for (int i = 0; i < 4; i++) {
                const int co = coB + ((i >> 1) << 3);
                const int n  = n0 + nwarp * 32 + nf * 8 + ((lane & 3) << 1) + (i & 1);
                const int bi = n / 36;
                const int pp = n - bi * 36;
                g_h2[(size_t)bi * 9216 + co * 36 + pp] =
                    acc[mf][nf][i] + ((i >> 1) ? bias1 : bias0);
            }
        }
    }
}

// ---------------------------------------------------------------------------
// primary capsule squash (unchanged)
// ---------------------------------------------------------------------------
__global__ __launch_bounds__(256) void k_squash_pc()
{
    unsigned idx = blockIdx.x * 256u + threadIdx.x;
    if (idx >= 589824u) return;
    const float4* p = (const float4*)(g_h2 + (size_t)idx * 8);
    float4 a = p[0], b = p[1];
    float sn = a.x*a.x + a.y*a.y + a.z*a.z + a.w*a.w
             + b.x*b.x + b.y*b.y + b.z*b.z + b.w*b.w;
    float sc = sn / ((1.f + sn) * (sqrtf(sn) + 1e-6f));
    a.x *= sc; a.y *= sc; a.z *= sc; a.w *= sc;
    b.x *= sc; b.y *= sc; b.z *= sc; b.w *= sc;
    float4* q = (float4*)(g_u + (size_t)idx * 8);
    q[0] = a; q[1] = b;
}

// ---------------------------------------------------------------------------
// u_hat -> fp16 (unchanged)
// ---------------------------------------------------------------------------
__global__ __launch_bounds__(256) void k_uhat(const float* __restrict__ W)
{
    __shared__ float Wsm[4 * 1280];
    __shared__ float usm[64 * 32];
    const int capg = blockIdx.x * 4;
    const int img0 = blockIdx.y * 64;
    const int id   = threadIdx.x;
    {
        const float4* Wg = (const float4*)(W + (size_t)capg * 1280);
        float4* Ws4 = (float4*)Wsm;
        for (int i = id; i < 1280; i += 256) Ws4[i] = Wg[i];
        float4* us4 = (float4*)usm;
        for (int i = id; i < 512; i += 256) {
            int im = i >> 3, r = i & 7;
            us4[i] = *(const float4*)(g_u + (size_t)(img0 + im) * 9216
                                      + capg * 8 + r * 4);
        }
    }
    __syncthreads();
    for (int it = 0; it < 40; it++) {
        int flat = it * 256 + id;
        int oe4  = flat % 40;
        int cap  = (flat / 40) & 3;
        int im   = flat / 160;
        int o    = oe4 >> 2;
        int e0   = (oe4 & 3) * 4;
        const float*  up = &usm[im * 32 + cap * 8];
        const float4* Wp = (const float4*)&Wsm[cap * 1280 + o * 128 + e0];
        float4 acc = make_float4(0.f, 0.f, 0.f, 0.f);
#pragma unroll
        for (int d = 0; d < 8; d++) {
            float  ud = up[d];
            float4 w4 = Wp[d * 4];
            acc.x = fmaf(ud, w4.x, acc.x);
            acc.y = fmaf(ud, w4.y, acc.y);
            acc.z = fmaf(ud, w4.z, acc.z);
            acc.w = fmaf(ud, w4.w, acc.w);
        }
        __half2 h0 = __floats2half2_rn(acc.x, acc.y);
        __half2 h1 = __floats2half2_rn(acc.z, acc.w);
        uint2 pk = make_uint2(*(uint32_t*)&h0, *(uint32_t*)&h1);
        *(uint2*)&g_uhat_h[((size_t)(img0 + im) * 1152 + capg + cap) * 160
                           + o * 16 + e0] = pk;
    }
}

// ---------------------------------------------------------------------------
// fused routing iteration, smem-staged (unchanged)
// ---------------------------------------------------------------------------
__global__ __launch_bounds__(160) void k_route(int uniform)
{
    __shared__ __align__(16) __half tile[128 * 168];
    __shared__ float vs[160];
    __shared__ float c_sm[128][10];
    const int b     = blockIdx.x;
    const int chunk = blockIdx.y;
    const int tid   = threadIdx.x;
    const __half* ub = g_uhat_h + (size_t)b * 184320 + (size_t)chunk * 128 * 160;

    if (uniform) {
        const int oe = tid;
        float acc = 0.f;
#pragma unroll 4
        for (int cap = 0; cap < 128; cap++)
            acc += __half2float(ub[(size_t)cap * 160 + oe]);
        g_spart[((size_t)chunk * 512 + b) * 160 + oe] = acc * 0.1f;
        return;
    }

    vs[tid] = g_vsum[b * 160 + tid];
    for (int f = tid; f < 2560; f += 160) {
        const int r = f / 20, j = f % 20;
        *(uint4*)&tile[r * 168 + j * 8] = *(const uint4*)(ub + (size_t)r * 160 + j * 8);
    }
    __syncthreads();

    if (tid < 128) {
        const __half2* row = (const __half2*)&tile[tid * 168];
        float t[10];
#pragma unroll
        for (int o = 0; o < 10; o++) {
            float s = 0.f;
#pragma unroll
            for (int e2 = 0; e2 < 8; e2++) {
                float2 f = __half22float2(row[o * 8 + e2]);
                s += f.x * vs[o * 16 + e2 * 2] + f.y * vs[o * 16 + e2 * 2 + 1];
            }
            t[o] = s;
        }
        float m = t[0];
#pragma unroll
        for (int o = 1; o < 10; o++) m = fmaxf(m, t[o]);
        float se = 0.f;
#pragma unroll
        for (int o = 0; o < 10; o++) { t[o] = expf(t[o] - m); se += t[o]; }
        float inv = 1.f / se;
#pragma unroll
        for (int o = 0; o < 10; o++) c_sm[tid][o] = t[o] * inv;
    }
    __syncthreads();

    const int oe = tid;
    const int o  = oe >> 4;
    float acc = 0.f;
#pragma unroll 4
    for (int cap = 0; cap < 128; cap++)
        acc = fmaf(c_sm[cap][o], __half2float(tile[cap * 168 + oe]), acc);
    g_spart[((size_t)chunk * 512 + b) * 160 + oe] = acc;
}

// ---------------------------------------------------------------------------
// sum partials + squash (unchanged)
// ---------------------------------------------------------------------------
__global__ void k_squash_v(float* __restrict__ out, int mode)
{
    int idx = blockIdx.x * 256 + threadIdx.x;
    if (idx >= 5120) return;
    float4 r[4];
#pragma unroll
    for (int i = 0; i < 4; i++) r[i] = make_float4(0.f, 0.f, 0.f, 0.f);
#pragma unroll
    for (int p = 0; p < 9; p++) {
        const float4* sp = (const float4*)(g_spart + (size_t)p * 81920
                                           + (size_t)idx * 16);
#pragma unroll
        for (int i = 0; i < 4; i++) {
            float4 v = sp[i];
            r[i].x += v.x; r[i].y += v.y; r[i].z += v.z; r[i].w += v.w;
        }
    }
    float sn = 0.f;
#pragma unroll
    for (int i = 0; i < 4; i++)
        sn += r[i].x*r[i].x + r[i].y*r[i].y + r[i].z*r[i].z + r[i].w*r[i].w;
    float sc = sn / ((1.f + sn) * (sqrtf(sn) + 1e-6f));
#pragma unroll
    for (int i = 0; i < 4; i++) {
        r[i].x *= sc; r[i].y *= sc; r[i].z *= sc; r[i].w *= sc;
    }
    if (mode == 0) {
        float4* q = (float4*)(g_vsum + (size_t)idx * 16);
#pragma unroll
        for (int i = 0; i < 4; i++) q[i] = r[i];
    } else if (mode == 1) {
        float4* q = (float4*)(g_vsum + (size_t)idx * 16);
#pragma unroll
        for (int i = 0; i < 4; i++) {
            float4 old = q[i];
            old.x += r[i].x; old.y += r[i].y; old.z += r[i].z; old.w += r[i].w;
            q[i] = old;
        }
    } else {
        float4* q = (float4*)(out + (size_t)idx * 16);
#pragma unroll
        for (int i = 0; i < 4; i++) q[i] = r[i];
    }
}

// ---------------------------------------------------------------------------
extern "C" void kernel_launch(void* const* d_in, const int* in_sizes, int n_in,
                              void* d_out, int out_size)
{
    const float* x   = (const float*)d_in[0];
    const float* w1  = (const float*)d_in[1];
    const float* b1  = (const float*)d_in[2];
    const float* w2  = (const float*)d_in[3];
    const float* b2  = (const float*)d_in[4];
    const float* W   = (const float*)d_in[5];
    float* out = (float*)d_out;

    cudaFuncSetAttribute(k_conv1mma,
                         cudaFuncAttributeMaxDynamicSharedMemorySize, 163872);
    cudaFuncSetAttribute(k_conv2mma,
                         cudaFuncAttributeMaxDynamicSharedMemorySize, 98336);

    k_im2col<<<512, 256>>>(x);
    k_w1prep<<<256, 256>>>(w1);
    k_wprep<<<256, 256>>>(w2);
    k_conv1mma<<<1600, 512, 163872>>>(b1);
    k_conv2mma<<<144, 512, 98336>>>(b2);
    k_squash_pc<<<2304, 256>>>();
    k_uhat<<<dim3(288, 8), 256>>>(W);

    k_route<<<dim3(512, 9), 160>>>(1);       // iter 0: uniform c
    k_squash_v<<<20, 256>>>(nullptr, 0);     // vsum = v0
    k_route<<<dim3(512, 9), 160>>>(0);       // iter 1
    k_squash_v<<<20, 256>>>(nullptr, 1);     // vsum += v1
    k_route<<<dim3(512, 9), 160>>>(0);       // iter 2
    k_squash_v<<<20, 256>>>(out, 2);         // out = v2
}

// round 12
// speedup vs baseline: 3.4175x; 1.1178x over previous
#include <cuda_runtime.h>
#include <cuda_fp16.h>
#include <cstdint>
#include <math.h>

// ===========================================================================
// CapsNet forward, B=512 — Round 12:
//  * conv1: single-fp16 weights (lo-term dropped) -> tensor work halved
//  * im2col: lane-invariant LUT hoisted to registers
//  * routing: b-chunked (2 x 256 images) so u_hat slice (94MB) stays in L2
// ===========================================================================

// ------------------------------ scratch ------------------------------------
__device__ __align__(128) __half g_x2col[512u * 400u * 256u];  // 105 MB
__device__ __align__(128) __half g_w1t [4u * 16384u];          // 128 KB
__device__ __align__(128) __half g_h1t [512u * 400u * 256u];   // 105 MB NHWC
__device__ __align__(128) __half g_w2t [81u * 4u * 16384u];    // 10.6 MB
__device__ float  g_h2[512u * 9216u];
__device__ float  g_u [512u * 9216u];
__device__ __half g_uhat_h[512u * 1152u * 160u];               // 188.7 MB
__device__ float  g_spart[9u * 512u * 160u];
__device__ float  g_vsum[512u * 160u];

// ------------------------------ PTX helpers --------------------------------
__device__ __forceinline__ uint32_t smem_u32(const void* p) {
    uint32_t a;
    asm("{ .reg .u64 t; cvta.to.shared.u64 t, %1; cvt.u32.u64 %0, t; }"
        : "=r"(a) : "l"(p));
    return a;
}
#define CP16(dst, src) \
    asm volatile("cp.async.cg.shared.global [%0], [%1], 16;" :: "r"(dst), "l"(src) : "memory")
#define CP_COMMIT() asm volatile("cp.async.commit_group;" ::: "memory")
#define CP_WAIT1()  asm volatile("cp.async.wait_group 1;" ::: "memory")
#define CP_WAIT0()  asm volatile("cp.async.wait_group 0;" ::: "memory")

#define MBAR_INIT(a, n) \
    asm volatile("mbarrier.init.shared.b64 [%0], %1;" :: "r"(a), "r"(n) : "memory")
#define MBAR_EXPECT_TX(a, bytes) \
    asm volatile("mbarrier.arrive.expect_tx.shared.b64 _, [%0], %1;" \
                 :: "r"(a), "r"(bytes) : "memory")
#define MBAR_WAIT(a, ph) do {                                                  \
    uint32_t _m = (a), _p = (ph), _d;                                          \
    asm volatile("{ .reg .pred p;"                                             \
        "mbarrier.try_wait.parity.acquire.cta.shared::cta.b64 p, [%1], %2;"    \
        "selp.b32 %0,1,0,p; }" : "=r"(_d) : "r"(_m), "r"(_p) : "memory");      \
    if (!_d) {                                                                 \
        asm volatile("{ .reg .pred P1; WL_%=:"                                 \
            "mbarrier.try_wait.parity.acquire.cta.shared::cta.b64 P1, [%0], %1, 0x989680;" \
            "@P1 bra.uni WD_%=; bra.uni WL_%=; WD_%=: }"                       \
            :: "r"(_m), "r"(_p) : "memory");                                   \
    }                                                                          \
} while (0)
#define BULK_G2S(dst, src, size, mbar) \
    asm volatile("cp.async.bulk.shared::cta.global.mbarrier::complete_tx::bytes " \
                 "[%0], [%1], %2, [%3];" \
                 :: "r"(dst), "l"(src), "r"(size), "r"(mbar) : "memory")

__device__ __forceinline__ void ldsm_x4(uint32_t* r, uint32_t addr) {
    asm volatile("ldmatrix.sync.aligned.m8n8.x4.shared.b16 {%0,%1,%2,%3}, [%4];"
                 : "=r"(r[0]), "=r"(r[1]), "=r"(r[2]), "=r"(r[3]) : "r"(addr));
}
__device__ __forceinline__ void mma16816h(float* c, const uint32_t* a,
                                          const uint32_t* b) {
    asm volatile("mma.sync.aligned.m16n8k16.row.col.f32.f16.f16.f32 "
                 "{%0,%1,%2,%3}, {%4,%5,%6,%7}, {%8,%9}, {%0,%1,%2,%3};"
                 : "+f"(c[0]), "+f"(c[1]), "+f"(c[2]), "+f"(c[3])
                 : "r"(a[0]), "r"(a[1]), "r"(a[2]), "r"(a[3]),
                   "r"(b[0]), "r"(b[1]));
}
__device__ __forceinline__ uint32_t swz(uint32_t o) {
    return o ^ ((o >> 3) & 0x70);
}

// ---------------------------------------------------------------------------
// im2col: x[b][3][28][28] -> x2col[b*400+pos][256] fp16. grid 512, block 256.
// Lane-invariant LUT kept in registers (loaded once per thread).
// ---------------------------------------------------------------------------
__global__ __launch_bounds__(256) void k_im2col(const float* __restrict__ x)
{
    __shared__ float xs[2352];
    const int b    = blockIdx.x;
    const int tid  = threadIdx.x;
    const int warp = tid >> 5;
    const int lane = tid & 31;
    {
        const float4* xg = (const float4*)(x + b * 2352);
        float4* xs4 = (float4*)xs;
        for (int i = tid; i < 588; i += 256) xs4[i] = xg[i];
    }
    int l[8];
#pragma unroll
    for (int j = 0; j < 8; j++) {
        const int k = lane * 8 + j;
        if (k < 243) {
            const int c = k / 81, kk = k - c * 81;
            const int ky = kk / 9, kx = kk - ky * 9;
            l[j] = c * 784 + ky * 28 + kx;
        } else l[j] = -1;
    }
    __syncthreads();

    for (int p = warp; p < 400; p += 8) {
        const int oy = p / 20, ox = p - (p / 20) * 20;
        const int off = oy * 28 + ox;
        __align__(16) __half vals[8];
#pragma unroll
        for (int j = 0; j < 8; j++)
            vals[j] = (l[j] >= 0) ? __float2half(xs[l[j] + off]) : __half(0.f);
        *(uint4*)&g_x2col[((size_t)b * 400 + p) * 256 + lane * 8] =
            *(const uint4*)vals;
    }
}

// ---------------------------------------------------------------------------
// w1[co][3][9][9] -> g_w1t chunked pre-swizzled single fp16. grid 256, blk 256.
// ---------------------------------------------------------------------------
__global__ __launch_bounds__(256) void k_w1prep(const float* __restrict__ w1)
{
    const int co = blockIdx.x;
    const int k  = threadIdx.x;
    float v = (k < 243) ? w1[co * 243 + k] : 0.f;
    const int cq  = k >> 6;
    const int k64 = k & 63;
    const uint32_t inner = swz((uint32_t)co * 128 + k64 * 2) >> 1;
    g_w1t[cq * 16384 + inner] = __float2half(v);
}

// ---------------------------------------------------------------------------
// conv1 GEMM: h1t[n][co] = relu(w1 @ x2col + b1). grid 1600, block 512.
// Stage 48KB: A[32K]|B[16K]; 2 stages; 4 K64 chunks; bulk A 32KB/chunk.
// ---------------------------------------------------------------------------
#define C1_STAGE 49152
#define C1_B_OFF 32768
#define C1_MB    98304
#define C1_NCH   4

__global__ __launch_bounds__(512) void k_conv1mma(const float* __restrict__ b1)
{
    extern __shared__ __align__(1024) char dynsmem[];
    const uint32_t sb = smem_u32(dynsmem);
    const int tid  = threadIdx.x;
    const int warp = tid >> 5;
    const int lane = tid & 31;
    const int n0    = blockIdx.x * 128;
    const int mwarp = warp & 3;       // co: mwarp*64
    const int nwarp = warp >> 2;      // n : nwarp*32

    if (tid == 0) {
        MBAR_INIT(sb + C1_MB, 1);
        MBAR_INIT(sb + C1_MB + 8, 1);
    }
    __syncthreads();

    const int uB = tid & 7;
    const int row0 = tid >> 3;
    const uint32_t pixBase0 = (uint32_t)(n0 + row0) * 256u + uB * 8;
    const uint32_t pixBase1 = (uint32_t)(n0 + row0 + 64) * 256u + uB * 8;
    const uint32_t bDst0 = swz((uint32_t)row0 * 128 + uB * 16);
    const uint32_t bDst1 = swz(((uint32_t)row0 + 64) * 128 + uB * 16);

    const int aRowSub = lane & 15;
    const int aColSel = (lane >> 4) * 16;
    const int bMat    = lane >> 3;
    const int bSub    = lane & 7;
    const int bNfSel  = bMat >> 1;
    const int bKSel   = (bMat & 1) * 16;

    float acc[4][4][4];
#pragma unroll
    for (int mf = 0; mf < 4; mf++)
#pragma unroll
        for (int nf = 0; nf < 4; nf++)
#pragma unroll
            for (int i = 0; i < 4; i++) acc[mf][nf][i] = 0.f;

    if (tid == 0) {
        MBAR_EXPECT_TX(sb + C1_MB, 32768);
        BULK_G2S(sb, (const char*)g_w1t, 32768, sb + C1_MB);
    }
    CP16(sb + C1_B_OFF + bDst0, g_x2col + pixBase0);
    CP16(sb + C1_B_OFF + bDst1, g_x2col + pixBase1);
    CP_COMMIT();

    for (int t = 0; t < C1_NCH; t++) {
        const int s = t & 1, s2 = s ^ 1;
        if (t + 1 < C1_NCH) {
            const int tn = t + 1;
            if (tid == 0) {
                MBAR_EXPECT_TX(sb + C1_MB + 8 * s2, 32768);
                BULK_G2S(sb + s2 * C1_STAGE,
                         (const char*)(g_w1t + (size_t)tn * 16384),
                         32768, sb + C1_MB + 8 * s2);
            }
            const int cOff = tn * 64;
            CP16(sb + s2 * C1_STAGE + C1_B_OFF + bDst0, g_x2col + pixBase0 + cOff);
            CP16(sb + s2 * C1_STAGE + C1_B_OFF + bDst1, g_x2col + pixBase1 + cOff);
            CP_COMMIT();
            CP_WAIT1();
        } else {
            CP_WAIT0();
        }
        MBAR_WAIT(sb + C1_MB + 8 * s, (t >> 1) & 1);
        __syncthreads();

        const uint32_t stb = sb + s * C1_STAGE;
        const uint32_t aa = stb;
        const uint32_t bb = stb + C1_B_OFF;

#pragma unroll
        for (int q = 0; q < 4; q++) {
            const int qb = q * 32;
            uint32_t B[4][2];
#pragma unroll
            for (int gp = 0; gp < 2; gp++) {
                uint32_t off = swz((nwarp * 32 + (gp * 2 + bNfSel) * 8 + bSub) * 128
                                   + qb + bKSel);
                uint32_t r[4];
                ldsm_x4(r, bb + off);
                B[gp*2][0] = r[0]; B[gp*2][1] = r[1];
                B[gp*2+1][0] = r[2]; B[gp*2+1][1] = r[3];
            }
#pragma unroll
            for (int mf = 0; mf < 4; mf++) {
                uint32_t A[4];
                uint32_t offA = swz((mwarp * 64 + mf * 16 + aRowSub) * 128
                                    + qb + aColSel);
                ldsm_x4(A, aa + offA);
#pragma unroll
                for (int nf = 0; nf < 4; nf++)
                    mma16816h(acc[mf][nf], A, B[nf]);
            }
        }
        __syncthreads();
    }

    // epilogue: bias + relu + fp16 via smem transpose -> coalesced h1t rows
    __half* ebuf = (__half*)dynsmem;
#pragma unroll
    for (int mf = 0; mf < 4; mf++) {
        const int coB = mwarp * 64 + mf * 16 + (lane >> 2);
        const float bias0 = b1[coB];
        const float bias1 = b1[coB + 8];
#pragma unroll
        for (int nf = 0; nf < 4; nf++) {
#pragma unroll
            for (int i = 0; i < 4; i++) {
                const int co = coB + ((i >> 1) << 3);
                const int nl = nwarp * 32 + nf * 8 + ((lane & 3) << 1) + (i & 1);
                const float v = acc[mf][nf][i] + ((i >> 1) ? bias1 : bias0);
                ebuf[nl * 256 + co] = __float2half(fmaxf(v, 0.f));
            }
        }
    }
    __syncthreads();
    for (int f = tid; f < 128 * 32; f += 512) {
        const int rw = f >> 5;
        const int j  = f & 31;
        *(uint4*)&g_h1t[(size_t)(n0 + rw) * 256 + j * 8] =
            *(const uint4*)&ebuf[rw * 256 + j * 8];
    }
}

// ---------------------------------------------------------------------------
// W2 prep (unchanged)
// ---------------------------------------------------------------------------
__global__ __launch_bounds__(256) void k_wprep(const float* __restrict__ w2)
{
    __shared__ float wt[128 * 81];
    const int co  = blockIdx.x;
    const int id  = threadIdx.x;
    const int c   = id & 127;
    const int hf  = id >> 7;

    for (int cc = 0; cc < 2; cc++) {
        __syncthreads();
        const float* src = w2 + (size_t)co * 20736 + cc * 128 * 81;
        for (int i = id; i < 128 * 81; i += 256) wt[i] = src[i];
        __syncthreads();
        const int cglob = cc * 128 + c;
        const int cq    = cglob >> 6;
        const int c64   = cglob & 63;
        const uint32_t inner = swz((uint32_t)co * 128 + c64 * 2) >> 1;
        const int k0 = hf ? 41 : 0;
        const int k1 = hf ? 81 : 41;
        for (int kk = k0; kk < k1; kk++) {
            g_w2t[(size_t)(kk * 4 + cq) * 16384 + inner] =
                __float2half(wt[c * 81 + kk]);
        }
    }
}

// ---------------------------------------------------------------------------
// conv2 implicit GEMM (unchanged R10). grid 144, block 512, 98336 B smem.
// ---------------------------------------------------------------------------
#define STAGE_BYTES 49152
#define A_BYTES 32768
#define B_OFF 32768
#define MB_OFF 98304
#define NCHUNK 324

__global__ __launch_bounds__(512) void k_conv2mma(const float* __restrict__ b2)
{
    extern __shared__ __align__(1024) char dynsmem[];
    const uint32_t sb = smem_u32(dynsmem);
    const int tid  = threadIdx.x;
    const int warp = tid >> 5;
    const int lane = tid & 31;
    const int n0    = blockIdx.x * 128;
    const int mwarp = warp & 3;
    const int nwarp = warp >> 2;

    if (tid == 0) {
        MBAR_INIT(sb + MB_OFF, 1);
        MBAR_INIT(sb + MB_OFF + 8, 1);
    }
    __syncthreads();

    const int uB = tid & 7;
    int pixBase[2];
#pragma unroll
    for (int h = 0; h < 2; h++) {
        const int n    = n0 + (tid >> 3) + h * 64;
        const int bimg = n / 36;
        const int pos  = n - bimg * 36;
        const int oy   = pos / 6, ox = pos - oy * 6;
        pixBase[h] = (bimg * 400 + oy * 40 + ox * 2) * 256 + uB * 8;
    }
    uint32_t bDst[2];
    bDst[0] = swz((uint32_t)(tid >> 3) * 128 + uB * 16);
    bDst[1] = swz(((uint32_t)(tid >> 3) + 64) * 128 + uB * 16);

    const int aRowSub = lane & 15;
    const int aColSel = (lane >> 4) * 16;
    const int bMat    = lane >> 3;
    const int bSub    = lane & 7;
    const int bNfSel  = bMat >> 1;
    const int bKSel   = (bMat & 1) * 16;

    float acc[4][4][4];
#pragma unroll
    for (int mf = 0; mf < 4; mf++)
#pragma unroll
        for (int nf = 0; nf < 4; nf++)
#pragma unroll
            for (int i = 0; i < 4; i++) acc[mf][nf][i] = 0.f;

    if (tid == 0) {
        MBAR_EXPECT_TX(sb + MB_OFF, A_BYTES);
        BULK_G2S(sb, (const char*)g_w2t, A_BYTES, sb + MB_OFF);
    }
#pragma unroll
    for (int h = 0; h < 2; h++)
        CP16(sb + B_OFF + bDst[h], g_h1t + pixBase[h]);
    CP_COMMIT();

    for (int t = 0; t < NCHUNK; t++) {
        const int s = t & 1, s2 = s ^ 1;
        if (t + 1 < NCHUNK) {
            const int tn = t + 1;
            const int kk = tn >> 2, cq = tn & 3;
            if (tid == 0) {
                MBAR_EXPECT_TX(sb + MB_OFF + 8 * s2, A_BYTES);
                BULK_G2S(sb + s2 * STAGE_BYTES,
                         (const char*)(g_w2t + (size_t)tn * 16384),
                         A_BYTES, sb + MB_OFF + 8 * s2);
            }
            const int ky = kk / 9, kx = kk - ky * 9;
            const int tap  = (ky * 20 + kx) * 256;
            const int cOff = cq * 64;
#pragma unroll
            for (int h = 0; h < 2; h++)
                CP16(sb + s2 * STAGE_BYTES + B_OFF + bDst[h],
                     g_h1t + pixBase[h] + tap + cOff);
            CP_COMMIT();
            CP_WAIT1();
        } else {
            CP_WAIT0();
        }
        MBAR_WAIT(sb + MB_OFF + 8 * s, (t >> 1) & 1);
        __syncthreads();

        const uint32_t stb = sb + s * STAGE_BYTES;
        const uint32_t aa = stb;
        const uint32_t bb = stb + B_OFF;

#pragma unroll
        for (int q = 0; q < 4; q++) {
            const int qb = q * 32;
            uint32_t B[4][2];
#pragma unroll
            for (int gp = 0; gp < 2; gp++) {
                uint32_t off = swz((nwarp * 32 + (gp * 2 + bNfSel) * 8 + bSub) * 128
                                   + qb + bKSel);
                uint32_t r[4];
                ldsm_x4(r, bb + off);
                B[gp*2][0] = r[0]; B[gp*2][1] = r[1];
                B[gp*2+1][0] = r[2]; B[gp*2+1][1] = r[3];
            }
#pragma unroll
            for (int mf = 0; mf < 4; mf++) {
                uint32_t A[4];
                uint32_t offA = swz((mwarp * 64 + mf * 16 + aRowSub) * 128
                                    + qb + aColSel);
                ldsm_x4(A, aa + offA);
#pragma unroll
                for (int nf = 0; nf < 4; nf++)
                    mma16816h(acc[mf][nf], A, B[nf]);
            }
        }
        __syncthreads();
    }

#pragma unroll
    for (int mf = 0; mf < 4; mf++) {
        const int coB = mwarp * 64 + mf * 16 + (lane >> 2);
        const float bias0 = b2[coB];
        const float bias1 = b2[coB + 8];
#pragma unroll
        for (int nf = 0; nf < 4; nf++) {
#pragma unroll
            for (int i = 0; i < 4; i++) {
                const int co = coB + ((i >> 1) << 3);
                const int n  = n0 + nwarp * 32 + nf * 8 + ((lane & 3) << 1) + (i & 1);
                const int bi = n / 36;
                const int pp = n - bi * 36;
                g_h2[(size_t)bi * 9216 + co * 36 + pp] =
                    acc[mf][nf][i] + ((i >> 1) ? bias1 : bias0);
            }
        }
    }
}

// ---------------------------------------------------------------------------
// primary capsule squash (unchanged)
// ---------------------------------------------------------------------------
__global__ __launch_bounds__(256) void k_squash_pc()
{
    unsigned idx = blockIdx.x * 256u + threadIdx.x;
    if (idx >= 589824u) return;
    const float4* p = (const float4*)(g_h2 + (size_t)idx * 8);
    float4 a = p[0], b = p[1];
    float sn = a.x*a.x + a.y*a.y + a.z*a.z + a.w*a.w
             + b.x*b.x + b.y*b.y + b.z*b.z + b.w*b.w;
    float sc = sn / ((1.f + sn) * (sqrtf(sn) + 1e-6f));
    a.x *= sc; a.y *= sc; a.z *= sc; a.w *= sc;
    b.x *= sc; b.y *= sc; b.z *= sc; b.w *= sc;
    float4* q = (float4*)(g_u + (size_t)idx * 8);
    q[0] = a; q[1] = b;
}

// ---------------------------------------------------------------------------
// u_hat -> fp16, b-chunked. grid (288, 4), block 256.
// ---------------------------------------------------------------------------
__global__ __launch_bounds__(256) void k_uhat(const float* __restrict__ W, int b0)
{
    __shared__ float Wsm[4 * 1280];
    __shared__ float usm[64 * 32];
    const int capg = blockIdx.x * 4;
    const int img0 = b0 + blockIdx.y * 64;
    const int id   = threadIdx.x;
    {
        const float4* Wg = (const float4*)(W + (size_t)capg * 1280);
        float4* Ws4 = (float4*)Wsm;
        for (int i = id; i < 1280; i += 256) Ws4[i] = Wg[i];
        float4* us4 = (float4*)usm;
        for (int i = id; i < 512; i += 256) {
            int im = i >> 3, r = i & 7;
            us4[i] = *(const float4*)(g_u + (size_t)(img0 + im) * 9216
                                      + capg * 8 + r * 4);
        }
    }
    __syncthreads();
    for (int it = 0; it < 40; it++) {
        int flat = it * 256 + id;
        int oe4  = flat % 40;
        int cap  = (flat / 40) & 3;
        int im   = flat / 160;
        int o    = oe4 >> 2;
        int e0   = (oe4 & 3) * 4;
        const float*  up = &usm[im * 32 + cap * 8];
        const float4* Wp = (const float4*)&Wsm[cap * 1280 + o * 128 + e0];
        float4 acc = make_float4(0.f, 0.f, 0.f, 0.f);
#pragma unroll
        for (int d = 0; d < 8; d++) {
            float  ud = up[d];
            float4 w4 = Wp[d * 4];
            acc.x = fmaf(ud, w4.x, acc.x);
            acc.y = fmaf(ud, w4.y, acc.y);
            acc.z = fmaf(ud, w4.z, acc.z);
            acc.w = fmaf(ud, w4.w, acc.w);
        }
        __half2 h0 = __floats2half2_rn(acc.x, acc.y);
        __half2 h1 = __floats2half2_rn(acc.z, acc.w);
        uint2 pk = make_uint2(*(uint32_t*)&h0, *(uint32_t*)&h1);
        *(uint2*)&g_uhat_h[((size_t)(img0 + im) * 1152 + capg + cap) * 160
                           + o * 16 + e0] = pk;
    }
}

// ---------------------------------------------------------------------------
// fused routing iteration, b-chunked. grid (256, 9), block 160.
// ---------------------------------------------------------------------------
__global__ __launch_bounds__(160) void k_route(int uniform, int b0)
{
    __shared__ __align__(16) __half tile[128 * 168];
    __shared__ float vs[160];
    __shared__ float c_sm[128][10];
    const int b     = b0 + blockIdx.x;
    const int chunk = blockIdx.y;
    const int tid   = threadIdx.x;
    const __half* ub = g_uhat_h + (size_t)b * 184320 + (size_t)chunk * 128 * 160;

    if (uniform) {
        const int oe = tid;
        float acc = 0.f;
#pragma unroll 4
        for (int cap = 0; cap < 128; cap++)
            acc += __half2float(ub[(size_t)cap * 160 + oe]);
        g_spart[((size_t)chunk * 512 + b) * 160 + oe] = acc * 0.1f;
        return;
    }

    vs[tid] = g_vsum[b * 160 + tid];
    for (int f = tid; f < 2560; f += 160) {
        const int r = f / 20, j = f % 20;
        *(uint4*)&tile[r * 168 + j * 8] = *(const uint4*)(ub + (size_t)r * 160 + j * 8);
    }
    __syncthreads();

    if (tid < 128) {
        const __half2* row = (const __half2*)&tile[tid * 168];
        float t[10];
#pragma unroll
        for (int o = 0; o < 10; o++) {
            float s = 0.f;
#pragma unroll
            for (int e2 = 0; e2 < 8; e2++) {
                float2 f = __half22float2(row[o * 8 + e2]);
                s += f.x * vs[o * 16 + e2 * 2] + f.y * vs[o * 16 + e2 * 2 + 1];
            }
            t[o] = s;
        }
        float m = t[0];
#pragma unroll
        for (int o = 1; o < 10; o++) m = fmaxf(m, t[o]);
        float se = 0.f;
#pragma unroll
        for (int o = 0; o < 10; o++) { t[o] = expf(t[o] - m); se += t[o]; }
        float inv = 1.f / se;
#pragma unroll
        for (int o = 0; o < 10; o++) c_sm[tid][o] = t[o] * inv;
    }
    __syncthreads();

    const int oe = tid;
    const int o  = oe >> 4;
    float acc = 0.f;
#pragma unroll 4
    for (int cap = 0; cap < 128; cap++)
        acc = fmaf(c_sm[cap][o], __half2float(tile[cap * 168 + oe]), acc);
    g_spart[((size_t)chunk * 512 + b) * 160 + oe] = acc;
}

// ---------------------------------------------------------------------------
// sum partials + squash, b-chunked. grid 10, block 256 (2560 (b,o) pairs).
// ---------------------------------------------------------------------------
__global__ void k_squash_v(float* __restrict__ out, int mode, int b0)
{
    int lidx = blockIdx.x * 256 + threadIdx.x;
    if (lidx >= 2560) return;
    const size_t idx = (size_t)b0 * 10 + lidx;     // global (b*10+o)
    float4 r[4];
#pragma unroll
    for (int i = 0; i < 4; i++) r[i] = make_float4(0.f, 0.f, 0.f, 0.f);
#pragma unroll
    for (int p = 0; p < 9; p++) {
        const float4* sp = (const float4*)(g_spart + (size_t)p * 81920
                                           + idx * 16);
#pragma unroll
        for (int i = 0; i < 4; i++) {
            float4 v = sp[i];
            r[i].x += v.x; r[i].y += v.y; r[i].z += v.z; r[i].w += v.w;
        }
    }
    float sn = 0.f;
#pragma unroll
    for (int i = 0; i < 4; i++)
        sn += r[i].x*r[i].x + r[i].y*r[i].y + r[i].z*r[i].z + r[i].w*r[i].w;
    float sc = sn / ((1.f + sn) * (sqrtf(sn) + 1e-6f));
#pragma unroll
    for (int i = 0; i < 4; i++) {
        r[i].x *= sc; r[i].y *= sc; r[i].z *= sc; r[i].w *= sc;
    }
    if (mode == 0) {
        float4* q = (float4*)(g_vsum + idx * 16);
#pragma unroll
        for (int i = 0; i < 4; i++) q[i] = r[i];
    } else if (mode == 1) {
        float4* q = (float4*)(g_vsum + idx * 16);
#pragma unroll
        for (int i = 0; i < 4; i++) {
            float4 old = q[i];
            old.x += r[i].x; old.y += r[i].y; old.z += r[i].z; old.w += r[i].w;
            q[i] = old;
        }
    } else {
        float4* q = (float4*)(out + idx * 16);
#pragma unroll
        for (int i = 0; i < 4; i++) q[i] = r[i];
    }
}

// ---------------------------------------------------------------------------
extern "C" void kernel_launch(void* const* d_in, const int* in_sizes, int n_in,
                              void* d_out, int out_size)
{
    const float* x   = (const float*)d_in[0];
    const float* w1  = (const float*)d_in[1];
    const float* b1  = (const float*)d_in[2];
    const float* w2  = (const float*)d_in[3];
    const float* b2  = (const float*)d_in[4];
    const float* W   = (const float*)d_in[5];
    float* out = (float*)d_out;

    cudaFuncSetAttribute(k_conv1mma,
                         cudaFuncAttributeMaxDynamicSharedMemorySize, 98368);
    cudaFuncSetAttribute(k_conv2mma,
                         cudaFuncAttributeMaxDynamicSharedMemorySize, 98336);

    k_im2col<<<512, 256>>>(x);
    k_w1prep<<<256, 256>>>(w1);
    k_wprep<<<256, 256>>>(w2);
    k_conv1mma<<<1600, 512, 98368>>>(b1);
    k_conv2mma<<<144, 512, 98336>>>(b2);
    k_squash_pc<<<2304, 256>>>();

    // routing tail, b-chunked (2 x 256 images) for L2-resident u_hat
    for (int c = 0; c < 2; c++) {
        const int b0 = c * 256;
        k_uhat<<<dim3(288, 4), 256>>>(W, b0);
        k_route<<<dim3(256, 9), 160>>>(1, b0);     // iter 0: uniform c
        k_squash_v<<<10, 256>>>(nullptr, 0, b0);   // vsum = v0
        k_route<<<dim3(256, 9), 160>>>(0, b0);     // iter 1
        k_squash_v<<<10, 256>>>(nullptr, 1, b0);   // vsum += v1
        k_route<<<dim3(256, 9), 160>>>(0, b0);     // iter 2
        k_squash_v<<<10, 256>>>(out, 2, b0);       // out = v2
    }
}